// round 1
// baseline (speedup 1.0000x reference)
#include <cuda_runtime.h>

#define BB   32
#define DIM  512
#define HWN  4096
#define KC   64
#define DQ   3
#define MM   192            // KC*DQ
#define TN   64
#define TD   16
#define NTILES (HWN/TN)     // 64

// Scratch (no allocation allowed in kernel_launch)
__device__ float g_kv[(size_t)BB * MM * HWN];       // ~100 MB
__device__ float g_part[BB * NTILES * KC];          // 131072 floats
__device__ int   g_code[BB];
__device__ float g_loss[BB * DQ];                   // 96 partials

// ---- packed f32x2 helpers (Blackwell-only PTX) ----
__device__ __forceinline__ void ffma2(unsigned long long& d,
                                      unsigned long long a,
                                      unsigned long long b) {
    asm("fma.rn.f32x2 %0, %1, %2, %0;" : "+l"(d) : "l"(a), "l"(b));
}
__device__ __forceinline__ unsigned long long pack2(float x) {
    unsigned long long r;
    asm("mov.b64 %0, {%1, %1};" : "=l"(r) : "f"(x));
    return r;
}

// ============================================================================
// Pass 1: O[b] = Wmat[192,512] @ feat[b][512,4096] tile-by-tile.
// Writes kv scratch + per-(b,tile,k) squared-distance partials.
// ============================================================================
__global__ __launch_bounds__(256, 2)
void kv_dist_kernel(const float* __restrict__ feat,
                    const float* __restrict__ query,
                    const float* __restrict__ Wm) {
    const int b    = blockIdx.y;
    const int tile = blockIdx.x;
    const int hw0  = tile * TN;
    const int tid  = threadIdx.x;
    const int mrow = tid >> 3;   // 0..31 -> m in [mrow*6, mrow*6+6)
    const int ncol = tid & 7;    // 0..7  -> n in [ncol*8, ncol*8+8)

    __shared__ __align__(16) float sW[TD][MM + 1];  // +1 pad: conflict-free transpose store
    __shared__ __align__(16) float sF[TD][TN];

    unsigned long long acc[6][4];
    #pragma unroll
    for (int i = 0; i < 6; i++)
        #pragma unroll
        for (int j = 0; j < 4; j++) acc[i][j] = 0ull;

    for (int dc = 0; dc < DIM; dc += TD) {
        // load W tile transposed: sW[dd][m]
        #pragma unroll
        for (int i = tid; i < MM * TD; i += 256) {
            int m  = i >> 4;
            int dd = i & 15;
            sW[dd][m] = Wm[m * DIM + dc + dd];
        }
        // load feature tile: sF[dd][n]
        #pragma unroll
        for (int i = tid; i < TD * TN; i += 256) {
            int dd = i >> 6;
            int n  = i & 63;
            sF[dd][n] = feat[(size_t)(b * DIM + dc + dd) * HWN + hw0 + n];
        }
        __syncthreads();

        #pragma unroll
        for (int dd = 0; dd < TD; dd++) {
            unsigned long long fv[4];
            #pragma unroll
            for (int j = 0; j < 4; j++)
                fv[j] = *(const unsigned long long*)&sF[dd][ncol * 8 + j * 2];
            #pragma unroll
            for (int i = 0; i < 6; i++) {
                unsigned long long wv = pack2(sW[dd][mrow * 6 + i]);
                #pragma unroll
                for (int j = 0; j < 4; j++)
                    ffma2(acc[i][j], wv, fv[j]);
            }
        }
        __syncthreads();
    }

    // --- epilogue: write kv, accumulate squared distances ---
    float dk0 = 0.f, dk1 = 0.f;   // two k's owned by this thread (k0 = mrow*2, k0+1)
    #pragma unroll
    for (int i = 0; i < 6; i++) {
        int m = mrow * 6 + i;
        float* dst = &g_kv[((size_t)b * MM + m) * HWN + hw0 + ncol * 8];
        const int qq = i % 3;    // mrow*6 is a multiple of 3
        const float* qp = &query[(size_t)(b * DQ + qq) * HWN + hw0 + ncol * 8];
        float s = 0.f;
        #pragma unroll
        for (int j = 0; j < 4; j++) {
            *(unsigned long long*)(dst + j * 2) = acc[i][j];
            float2 o  = *(float2*)&acc[i][j];
            float2 qv = *(const float2*)(qp + j * 2);
            float d0 = o.x - qv.x;
            float d1 = o.y - qv.y;
            s += d0 * d0 + d1 * d1;
        }
        if (i < 3) dk0 += s; else dk1 += s;
    }
    // reduce across the 8 ncol lanes (same mrow group inside the warp)
    #pragma unroll
    for (int off = 1; off < 8; off <<= 1) {
        dk0 += __shfl_xor_sync(0xffffffff, dk0, off);
        dk1 += __shfl_xor_sync(0xffffffff, dk1, off);
    }
    if (ncol == 0) {
        int k0 = mrow * 2;
        g_part[(b * NTILES + tile) * KC + k0]     = dk0;
        g_part[(b * NTILES + tile) * KC + k0 + 1] = dk1;
    }
}

// ============================================================================
// Pass 2: fixed-order tile sum + argmin (first-min tie-break like jnp.argmin)
// ============================================================================
__global__ void argmin_kernel(float* __restrict__ out_codes) {
    const int b = blockIdx.x;
    const int k = threadIdx.x;   // 64 threads
    float s = 0.f;
    for (int t = 0; t < NTILES; t++)
        s += g_part[(b * NTILES + t) * KC + k];

    __shared__ float sv[KC];
    __shared__ int   si[KC];
    sv[k] = s; si[k] = k;
    __syncthreads();
    for (int off = 32; off > 0; off >>= 1) {
        if (k < off) {
            float ov = sv[k + off];
            int   oi = si[k + off];
            if (ov < sv[k] || (ov == sv[k] && oi < si[k])) { sv[k] = ov; si[k] = oi; }
        }
        __syncthreads();
    }
    if (k == 0) {
        g_code[b] = si[0];
        out_codes[b] = (float)si[0];
    }
}

// ============================================================================
// Pass 3: gather selected kv rows + loss partials (fixed-order reductions)
// ============================================================================
__global__ __launch_bounds__(256)
void gather_loss_kernel(const float* __restrict__ query,
                        float* __restrict__ out_sel) {
    const int blk = blockIdx.x;      // 0..95
    const int b   = blk / DQ;
    const int qq  = blk % DQ;
    const int tid = threadIdx.x;
    const int code = g_code[b];

    const float* src = &g_kv[((size_t)b * MM + code * DQ + qq) * HWN];
    const float* qp  = &query[(size_t)(b * DQ + qq) * HWN];
    float*       dst = &out_sel[(size_t)(b * DQ + qq) * HWN];

    float s = 0.f;
    for (int i = tid; i < HWN; i += 256) {
        float v = src[i];
        dst[i] = v;
        float d = v - qp[i];
        s += d * d;
    }
    __shared__ float red[256];
    red[tid] = s;
    __syncthreads();
    for (int off = 128; off > 0; off >>= 1) {
        if (tid < off) red[tid] += red[tid + off];
        __syncthreads();
    }
    if (tid == 0) g_loss[blk] = red[0];
}

__global__ void loss_final_kernel(float* __restrict__ out_loss) {
    if (threadIdx.x == 0) {
        float s = 0.f;
        for (int i = 0; i < BB * DQ; i++) s += g_loss[i];
        *out_loss = s / (float)((size_t)BB * DQ * HWN);
    }
}

// ============================================================================
extern "C" void kernel_launch(void* const* d_in, const int* in_sizes, int n_in,
                              void* d_out, int out_size) {
    const float* feat  = (const float*)d_in[0];
    const float* query = (const float*)d_in[1];
    const float* Wm    = (const float*)d_in[2];
    float* out = (float*)d_out;

    dim3 g1(NTILES, BB);
    kv_dist_kernel<<<g1, 256>>>(feat, query, Wm);
    argmin_kernel<<<BB, KC>>>(out + (size_t)BB * DQ * HWN);
    gather_loss_kernel<<<BB * DQ, 256>>>(query, out);
    loss_final_kernel<<<1, 32>>>(out + (size_t)BB * DQ * HWN + BB);
}

// round 3
// speedup vs baseline: 2.8534x; 2.8534x over previous
#include <cuda_runtime.h>
#include <cuda_bf16.h>
#include <cstdint>

#define BB   32
#define DIM  512
#define HWN  4096
#define KC   64
#define DQ   3
#define MM   192
#define NTILE 128           // hw per CTA
#define NT   32             // 4096/128
#define KSTAGE 32
#define NSTAGE 16           // 512/32

#define F_PITCH 132         // floats per k-row in smem (128 + 4 pad)
#define OFF_WHI 0
#define OFF_WLO 15360       // 192 * 80
#define OFF_F   30720
#define STAGE_B 47616       // 30720 + 32*132*4

// ---------------- scratch ----------------
__device__ float    g_kv[(size_t)BB * MM * HWN];     // [b][m][hw]
__device__ float    g_part[BB * NT * KC];
__device__ int      g_code[BB];
__device__ float    g_loss[BB * DQ];
__device__ unsigned g_Whi[MM * DIM / 2];             // bf16x2, [m][kpair]
__device__ unsigned g_Wlo[MM * DIM / 2];

// ---------------- helpers ----------------
__device__ __forceinline__ uint32_t smem_u32(const void* p) {
    uint32_t a;
    asm("{ .reg .u64 t; cvta.to.shared.u64 t, %1; cvt.u32.u64 %0, t; }" : "=r"(a) : "l"(p));
    return a;
}
__device__ __forceinline__ void cp16(uint32_t smem, const void* gmem) {
    unsigned long long ga = (unsigned long long)__cvta_generic_to_global(gmem);
    asm volatile("cp.async.cg.shared.global [%0], [%1], 16;" :: "r"(smem), "l"(ga));
}
__device__ __forceinline__ void cp_commit() { asm volatile("cp.async.commit_group;"); }
__device__ __forceinline__ void cp_wait1() { asm volatile("cp.async.wait_group 1;" ::: "memory"); }
__device__ __forceinline__ void cp_wait0() { asm volatile("cp.async.wait_group 0;" ::: "memory"); }

__device__ __forceinline__ void ldm4(unsigned* r, uint32_t a) {
    asm volatile("ldmatrix.sync.aligned.m8n8.x4.shared.b16 {%0,%1,%2,%3}, [%4];"
                 : "=r"(r[0]), "=r"(r[1]), "=r"(r[2]), "=r"(r[3]) : "r"(a));
}
__device__ __forceinline__ void mma16816(float* c, const unsigned* a, const unsigned* b) {
    asm volatile("mma.sync.aligned.m16n8k16.row.col.f32.bf16.bf16.f32 "
                 "{%0,%1,%2,%3}, {%4,%5,%6,%7}, {%8,%9}, {%0,%1,%2,%3};"
                 : "+f"(c[0]), "+f"(c[1]), "+f"(c[2]), "+f"(c[3])
                 : "r"(a[0]), "r"(a[1]), "r"(a[2]), "r"(a[3]), "r"(b[0]), "r"(b[1]));
}
// pack {hi=x1 (k odd), lo=x0 (k even)}
__device__ __forceinline__ unsigned cvt2(float x0, float x1) {
    unsigned r;
    asm("cvt.rn.bf16x2.f32 %0, %1, %2;" : "=r"(r) : "f"(x1), "f"(x0));
    return r;
}
__device__ __forceinline__ float lo_f32(unsigned r)  { return __uint_as_float(r << 16); }
__device__ __forceinline__ float hi_f32(unsigned r)  { return __uint_as_float(r & 0xffff0000u); }

// ============================================================================
// Pass 0: split W fp32 -> bf16 hi/lo packed k-pairs
// ============================================================================
__global__ void wsplit_kernel(const float* __restrict__ W) {
    int i = blockIdx.x * 256 + threadIdx.x;   // pair index: [m][kpair]
    if (i >= MM * DIM / 2) return;
    float x0 = W[2 * i], x1 = W[2 * i + 1];
    unsigned h = cvt2(x0, x1);
    g_Whi[i] = h;
    g_Wlo[i] = cvt2(x0 - lo_f32(h), x1 - hi_f32(h));
}

// ============================================================================
// Pass 1: C[m,hw] = W @ feat per batch via mma.sync bf16x3.
// grid (NT=32, BB=32), 256 threads (8 warps: 2 m x 4 n), cp.async double buffer.
// ============================================================================
__global__ __launch_bounds__(256)
void kv_mma_kernel(const float* __restrict__ feat,
                   const float* __restrict__ query) {
    extern __shared__ __align__(16) unsigned char dyn[];
    __shared__ float sdist[MM][4];

    const int tid  = threadIdx.x;
    const int b    = blockIdx.y;
    const int hw0  = blockIdx.x * NTILE;
    const int lane = tid & 31, wid = tid >> 5;
    const int warp_m = wid >> 2;          // 0..1 -> m offset *96
    const int warp_n = wid & 3;           // 0..3 -> hw offset *32
    const int g  = lane >> 2, tg = lane & 3;

    const uint32_t sbase = smem_u32(dyn);

    auto issue = [&](int s, int buf) {
        const uint32_t bb = sbase + (uint32_t)buf * STAGE_B;
        #pragma unroll
        for (int j = 0; j < 4; j++) {                // feat: 32 rows x 32 chunks
            int i = tid + j * 256;
            int kk = i >> 5, c = i & 31;
            cp16(bb + OFF_F + kk * (F_PITCH * 4) + c * 16,
                 feat + ((size_t)(b * DIM + s * KSTAGE + kk)) * HWN + hw0 + c * 4);
        }
        #pragma unroll
        for (int j = 0; j < 3; j++) {                // W hi/lo: 192 rows x 4 chunks
            int i = tid + j * 256;
            int m = i >> 2, c = i & 3;
            cp16(bb + OFF_WHI + m * 80 + c * 16, g_Whi + m * 256 + s * 16 + c * 4);
            cp16(bb + OFF_WLO + m * 80 + c * 16, g_Wlo + m * 256 + s * 16 + c * 4);
        }
    };

    float acc[6][4][4];
    #pragma unroll
    for (int mi = 0; mi < 6; mi++)
        #pragma unroll
        for (int ni = 0; ni < 4; ni++)
            #pragma unroll
            for (int r = 0; r < 4; r++) acc[mi][ni][r] = 0.f;

    issue(0, 0); cp_commit();

    for (int s = 0; s < NSTAGE; s++) {
        const int buf = s & 1;
        if (s + 1 < NSTAGE) { issue(s + 1, buf ^ 1); cp_commit(); cp_wait1(); }
        else cp_wait0();
        __syncthreads();

        const uint32_t wbh = sbase + (uint32_t)buf * STAGE_B + OFF_WHI;
        const uint32_t wbl = wbh + (OFF_WLO - OFF_WHI);
        const float* fb = (const float*)(dyn + (size_t)buf * STAGE_B + OFF_F);

        #pragma unroll
        for (int ks = 0; ks < 2; ks++) {
            // ---- B fragments: fp32 gather -> bf16 hi/lo ----
            unsigned bh[4][2], bl[4][2];
            #pragma unroll
            for (int ni = 0; ni < 4; ni++) {
                int n  = warp_n * 32 + ni * 8 + g;
                int k0 = ks * 16 + 2 * tg;
                float x0 = fb[(k0    ) * F_PITCH + n];
                float x1 = fb[(k0 + 1) * F_PITCH + n];
                float x2 = fb[(k0 + 8) * F_PITCH + n];
                float x3 = fb[(k0 + 9) * F_PITCH + n];
                unsigned h0 = cvt2(x0, x1), h1 = cvt2(x2, x3);
                bh[ni][0] = h0; bh[ni][1] = h1;
                bl[ni][0] = cvt2(x0 - lo_f32(h0), x1 - hi_f32(h0));
                bl[ni][1] = cvt2(x2 - lo_f32(h1), x3 - hi_f32(h1));
            }
            // ---- A fragments per m-tile + 3-pass mma ----
            #pragma unroll
            for (int mi = 0; mi < 6; mi++) {
                uint32_t aoff = (uint32_t)(warp_m * 96 + mi * 16 + (lane & 15)) * 80
                              + ks * 32 + (lane >> 4) * 16;
                unsigned ah[4], al[4];
                ldm4(ah, wbh + aoff);
                ldm4(al, wbl + aoff);
                #pragma unroll
                for (int ni = 0; ni < 4; ni++) {
                    mma16816(acc[mi][ni], ah, bh[ni]);
                    mma16816(acc[mi][ni], al, bh[ni]);
                    mma16816(acc[mi][ni], ah, bl[ni]);
                }
            }
        }
        __syncthreads();
    }

    // ---- epilogue: write kv + fixed-order distance partials ----
    float2 qv[4][3];
    #pragma unroll
    for (int ni = 0; ni < 4; ni++) {
        int hw = hw0 + warp_n * 32 + ni * 8 + 2 * tg;
        #pragma unroll
        for (int qq = 0; qq < 3; qq++)
            qv[ni][qq] = *(const float2*)&query[((size_t)b * DQ + qq) * HWN + hw];
    }

    #pragma unroll
    for (int mi = 0; mi < 6; mi++) {
        int m0 = warp_m * 96 + mi * 16 + g;
        int q0 = m0 % 3, q1 = (m0 + 8) % 3;
        float d0 = 0.f, d1 = 0.f;
        #pragma unroll
        for (int ni = 0; ni < 4; ni++) {
            int hw = hw0 + warp_n * 32 + ni * 8 + 2 * tg;
            float2 p0 = make_float2(acc[mi][ni][0], acc[mi][ni][1]);
            float2 p1 = make_float2(acc[mi][ni][2], acc[mi][ni][3]);
            *(float2*)&g_kv[((size_t)b * MM + m0    ) * HWN + hw] = p0;
            *(float2*)&g_kv[((size_t)b * MM + m0 + 8) * HWN + hw] = p1;
            float e0 = p0.x - qv[ni][q0].x, e1 = p0.y - qv[ni][q0].y;
            d0 += e0 * e0 + e1 * e1;
            float f0 = p1.x - qv[ni][q1].x, f1 = p1.y - qv[ni][q1].y;
            d1 += f0 * f0 + f1 * f1;
        }
        d0 += __shfl_xor_sync(0xffffffffu, d0, 1);
        d0 += __shfl_xor_sync(0xffffffffu, d0, 2);
        d1 += __shfl_xor_sync(0xffffffffu, d1, 1);
        d1 += __shfl_xor_sync(0xffffffffu, d1, 2);
        if (tg == 0) {
            sdist[m0][warp_n]     = d0;
            sdist[m0 + 8][warp_n] = d1;
        }
    }
    __syncthreads();
    if (tid < KC) {
        float s = 0.f;
        #pragma unroll
        for (int qq = 0; qq < 3; qq++)
            #pragma unroll
            for (int wn = 0; wn < 4; wn++)
                s += sdist[tid * 3 + qq][wn];
        g_part[((size_t)b * NT + blockIdx.x) * KC + tid] = s;
    }
}

// ============================================================================
// Pass 2: fixed-order tile sum + argmin (first-min tie-break)
// ============================================================================
__global__ void argmin_kernel(float* __restrict__ out_codes) {
    const int b = blockIdx.x;
    const int k = threadIdx.x;   // 64
    float s = 0.f;
    for (int tt = 0; tt < NT; tt++)
        s += g_part[(b * NT + tt) * KC + k];

    __shared__ float sv[KC];
    __shared__ int   si[KC];
    sv[k] = s; si[k] = k;
    __syncthreads();
    for (int off = 32; off > 0; off >>= 1) {
        if (k < off) {
            float ov = sv[k + off];
            int   oi = si[k + off];
            if (ov < sv[k] || (ov == sv[k] && oi < si[k])) { sv[k] = ov; si[k] = oi; }
        }
        __syncthreads();
    }
    if (k == 0) {
        g_code[b] = si[0];
        out_codes[b] = (float)si[0];
    }
}

// ============================================================================
// Pass 3: gather selected kv rows + loss partials
// ============================================================================
__global__ __launch_bounds__(256)
void gather_loss_kernel(const float* __restrict__ query,
                        float* __restrict__ out_sel) {
    const int blk = blockIdx.x;      // 0..95
    const int b   = blk / DQ;
    const int qq  = blk % DQ;
    const int tid = threadIdx.x;
    const int code = g_code[b];

    const float* src = &g_kv[((size_t)b * MM + code * DQ + qq) * HWN];
    const float* qp  = &query[(size_t)(b * DQ + qq) * HWN];
    float*       dst = &out_sel[(size_t)(b * DQ + qq) * HWN];

    float s = 0.f;
    for (int i = tid; i < HWN; i += 256) {
        float v = src[i];
        dst[i] = v;
        float d = v - qp[i];
        s += d * d;
    }
    __shared__ float red[256];
    red[tid] = s;
    __syncthreads();
    for (int off = 128; off > 0; off >>= 1) {
        if (tid < off) red[tid] += red[tid + off];
        __syncthreads();
    }
    if (tid == 0) g_loss[blk] = red[0];
}

__global__ void loss_final_kernel(float* __restrict__ out_loss) {
    if (threadIdx.x == 0) {
        float s = 0.f;
        for (int i = 0; i < BB * DQ; i++) s += g_loss[i];
        *out_loss = s / (float)((size_t)BB * DQ * HWN);
    }
}

// ============================================================================
extern "C" void kernel_launch(void* const* d_in, const int* in_sizes, int n_in,
                              void* d_out, int out_size) {
    const float* feat  = (const float*)d_in[0];
    const float* query = (const float*)d_in[1];
    const float* Wm    = (const float*)d_in[2];
    float* out = (float*)d_out;

    cudaFuncSetAttribute((const void*)kv_mma_kernel,
                         cudaFuncAttributeMaxDynamicSharedMemorySize, 2 * STAGE_B);

    wsplit_kernel<<<192, 256>>>(Wm);
    dim3 g1(NT, BB);
    kv_mma_kernel<<<g1, 256, 2 * STAGE_B>>>(feat, query);
    argmin_kernel<<<BB, KC>>>(out + (size_t)BB * DQ * HWN);
    gather_loss_kernel<<<BB * DQ, 256>>>(query, out);
    loss_final_kernel<<<1, 32>>>(out + (size_t)BB * DQ * HWN + BB);
}

// round 4
// speedup vs baseline: 2.9810x; 1.0447x over previous
#include <cuda_runtime.h>
#include <cuda_bf16.h>
#include <cstdint>

#define BB   32
#define DIM  512
#define HWN  4096
#define KC   64
#define DQ   3
#define MM   192
#define NTILE 128           // hw per CTA
#define NT   32             // 4096/128
#define KSTAGE 32
#define NSTAGE 16           // 512/32

// dynamic smem layout
#define W_BUF_B   30720     // per buffer: hi 15360 (192*80) + lo 15360
#define OFF_W     0
#define OFF_F     61440     // fp32 feat stage: 2 x 16384  ([k32][n128] fp32)
#define OFF_BH    94208     // bf16 hi [k32][n128], swizzled, 8192
#define OFF_BL    102400
#define SMEM_TOT  110592

// ---------------- scratch ----------------
__device__ float    g_kv[(size_t)BB * MM * HWN];     // [b][m][hw]
__device__ float    g_part[BB * NT * KC];
__device__ int      g_code[BB];
__device__ float    g_loss[BB * DQ * 4];
__device__ unsigned g_Whi[MM * DIM / 2];             // bf16x2, [m][kpair]
__device__ unsigned g_Wlo[MM * DIM / 2];

// ---------------- helpers ----------------
__device__ __forceinline__ uint32_t smem_u32(const void* p) {
    uint32_t a;
    asm("{ .reg .u64 t; cvta.to.shared.u64 t, %1; cvt.u32.u64 %0, t; }" : "=r"(a) : "l"(p));
    return a;
}
__device__ __forceinline__ void cp16(uint32_t smem, const void* gmem) {
    unsigned long long ga = (unsigned long long)__cvta_generic_to_global(gmem);
    asm volatile("cp.async.cg.shared.global [%0], [%1], 16;" :: "r"(smem), "l"(ga));
}
__device__ __forceinline__ void cp_commit() { asm volatile("cp.async.commit_group;"); }
__device__ __forceinline__ void cp_wait0() { asm volatile("cp.async.wait_group 0;" ::: "memory"); }

__device__ __forceinline__ void ldm4(unsigned* r, uint32_t a) {
    asm volatile("ldmatrix.sync.aligned.m8n8.x4.shared.b16 {%0,%1,%2,%3}, [%4];"
                 : "=r"(r[0]), "=r"(r[1]), "=r"(r[2]), "=r"(r[3]) : "r"(a));
}
__device__ __forceinline__ void ldm4t(unsigned* r, uint32_t a) {
    asm volatile("ldmatrix.sync.aligned.m8n8.x4.trans.shared.b16 {%0,%1,%2,%3}, [%4];"
                 : "=r"(r[0]), "=r"(r[1]), "=r"(r[2]), "=r"(r[3]) : "r"(a));
}
__device__ __forceinline__ void mma16816(float* c, const unsigned* a, const unsigned* b) {
    asm volatile("mma.sync.aligned.m16n8k16.row.col.f32.bf16.bf16.f32 "
                 "{%0,%1,%2,%3}, {%4,%5,%6,%7}, {%8,%9}, {%0,%1,%2,%3};"
                 : "+f"(c[0]), "+f"(c[1]), "+f"(c[2]), "+f"(c[3])
                 : "r"(a[0]), "r"(a[1]), "r"(a[2]), "r"(a[3]), "r"(b[0]), "r"(b[1]));
}
// pack {lo half = x0, hi half = x1}
__device__ __forceinline__ unsigned cvt2(float x0, float x1) {
    unsigned r;
    asm("cvt.rn.bf16x2.f32 %0, %1, %2;" : "=r"(r) : "f"(x1), "f"(x0));
    return r;
}
__device__ __forceinline__ float lo_f32(unsigned r)  { return __uint_as_float(r << 16); }
__device__ __forceinline__ float hi_f32(unsigned r)  { return __uint_as_float(r & 0xffff0000u); }

// ============================================================================
// Pass 0: split W fp32 -> bf16 hi/lo packed k-pairs
// ============================================================================
__global__ void wsplit_kernel(const float* __restrict__ W) {
    int i = blockIdx.x * 256 + threadIdx.x;
    if (i >= MM * DIM / 2) return;
    float x0 = W[2 * i], x1 = W[2 * i + 1];
    unsigned h = cvt2(x0, x1);
    g_Whi[i] = h;
    g_Wlo[i] = cvt2(x0 - lo_f32(h), x1 - hi_f32(h));
}

// ============================================================================
// Pass 1: C[m,hw] = W @ feat per batch via mma.sync bf16x3.
// 256 threads (8 warps: 2m x 4n). Cooperative bf16 conversion + ldmatrix.trans.
// ============================================================================
__global__ __launch_bounds__(256)
void kv_mma_kernel(const float* __restrict__ feat,
                   const float* __restrict__ query) {
    extern __shared__ __align__(16) unsigned char dyn[];
    __shared__ float sdist[MM][4];

    const int tid  = threadIdx.x;
    const int b    = blockIdx.y;
    const int hw0  = blockIdx.x * NTILE;
    const int lane = tid & 31, wid = tid >> 5;
    const int warp_m = wid >> 2;          // 0..1 -> m offset *96
    const int warp_n = wid & 3;           // 0..3 -> hw offset *32
    const int g  = lane >> 2, tg = lane & 3;

    const uint32_t sbase = smem_u32(dyn);

    auto issue = [&](int s, int buf) {
        const uint32_t fb = sbase + OFF_F + (uint32_t)buf * 16384;
        #pragma unroll
        for (int j = 0; j < 4; j++) {                // feat: 32 rows x 32 chunks
            int i = tid + j * 256;
            int kk = i >> 5, c = i & 31;
            cp16(fb + kk * 512 + c * 16,
                 feat + ((size_t)(b * DIM + s * KSTAGE + kk)) * HWN + hw0 + c * 4);
        }
        const uint32_t wb = sbase + OFF_W + (uint32_t)buf * W_BUF_B;
        #pragma unroll
        for (int j = 0; j < 3; j++) {                // W hi/lo: 192 rows x 4 chunks
            int i = tid + j * 256;
            int m = i >> 2, c = i & 3;
            cp16(wb + m * 80 + c * 16,         g_Whi + m * 256 + s * 16 + c * 4);
            cp16(wb + 15360 + m * 80 + c * 16, g_Wlo + m * 256 + s * 16 + c * 4);
        }
    };

    float acc[6][4][4];
    #pragma unroll
    for (int mi = 0; mi < 6; mi++)
        #pragma unroll
        for (int ni = 0; ni < 4; ni++)
            #pragma unroll
            for (int r = 0; r < 4; r++) acc[mi][ni][r] = 0.f;

    // precomputed B ldmatrix lane addressing (k = lane-dependent row)
    const int b_r      = lane & 7;               // row within 8x8
    const int b_khalf  = (lane >> 3) & 1;        // +8 k
    const int b_nhalf  = (lane >> 4) & 1;        // +8 n
    const uint32_t b_ncol0 = (uint32_t)(warp_n * 32 + b_nhalf * 8);

    issue(0, 0); cp_commit();

    for (int s = 0; s < NSTAGE; s++) {
        const int buf = s & 1;
        cp_wait0();
        __syncthreads();

        // ---- cooperative fp32 -> bf16 hi/lo conversion ----
        {
            const float* fsrc = (const float*)(dyn + OFF_F + (size_t)buf * 16384);
            #pragma unroll
            for (int p = 0; p < 2; p++) {
                int k = wid * 4 + p * 2 + (lane >> 4);
                int l = lane & 15;
                float4 v0 = *(const float4*)(fsrc + k * 128 + l * 8);
                float4 v1 = *(const float4*)(fsrc + k * 128 + l * 8 + 4);
                unsigned h0 = cvt2(v0.x, v0.y), h1 = cvt2(v0.z, v0.w);
                unsigned h2 = cvt2(v1.x, v1.y), h3 = cvt2(v1.z, v1.w);
                unsigned l0 = cvt2(v0.x - lo_f32(h0), v0.y - hi_f32(h0));
                unsigned l1 = cvt2(v0.z - lo_f32(h1), v0.w - hi_f32(h1));
                unsigned l2 = cvt2(v1.x - lo_f32(h2), v1.y - hi_f32(h2));
                unsigned l3 = cvt2(v1.z - lo_f32(h3), v1.w - hi_f32(h3));
                uint32_t off = (uint32_t)(k * 256 + ((l * 16) ^ ((k & 7) << 4)));
                *(uint4*)(dyn + OFF_BH + off) = make_uint4(h0, h1, h2, h3);
                *(uint4*)(dyn + OFF_BL + off) = make_uint4(l0, l1, l2, l3);
            }
        }
        __syncthreads();

        if (s + 1 < NSTAGE) { issue(s + 1, buf ^ 1); cp_commit(); }

        const uint32_t wbh = sbase + OFF_W + (uint32_t)buf * W_BUF_B;
        const uint32_t wbl = wbh + 15360;

        #pragma unroll
        for (int ks = 0; ks < 2; ks++) {
            // ---- B fragments via ldmatrix.trans ----
            unsigned bh[2][4], bl[2][4];
            {
                uint32_t k = (uint32_t)(ks * 16 + b_khalf * 8 + b_r);
                uint32_t rowb = sbase + k * 256;
                uint32_t sw = (uint32_t)(b_r << 4);
                #pragma unroll
                for (int half = 0; half < 2; half++) {
                    uint32_t coff = (((b_ncol0 + half * 16) * 2) ^ sw);
                    ldm4t(bh[half], rowb + OFF_BH + coff);
                    ldm4t(bl[half], rowb + OFF_BL + coff);
                }
            }
            // ---- A frags per m-tile + 3-pass mma (dep distance 4) ----
            #pragma unroll
            for (int mi = 0; mi < 6; mi++) {
                uint32_t aoff = (uint32_t)(warp_m * 96 + mi * 16 + (lane & 15)) * 80
                              + ks * 32 + (lane >> 4) * 16;
                unsigned ah[4], al[4];
                ldm4(ah, wbh + aoff);
                ldm4(al, wbl + aoff);
                #pragma unroll
                for (int ni = 0; ni < 4; ni++)
                    mma16816(acc[mi][ni], ah, &bh[ni >> 1][(ni & 1) * 2]);
                #pragma unroll
                for (int ni = 0; ni < 4; ni++)
                    mma16816(acc[mi][ni], al, &bh[ni >> 1][(ni & 1) * 2]);
                #pragma unroll
                for (int ni = 0; ni < 4; ni++)
                    mma16816(acc[mi][ni], ah, &bl[ni >> 1][(ni & 1) * 2]);
            }
        }
        __syncthreads();
    }

    // ---- epilogue: write kv + fixed-order distance partials ----
    float2 qv[4][3];
    #pragma unroll
    for (int ni = 0; ni < 4; ni++) {
        int hw = hw0 + warp_n * 32 + ni * 8 + 2 * tg;
        #pragma unroll
        for (int qq = 0; qq < 3; qq++)
            qv[ni][qq] = *(const float2*)&query[((size_t)b * DQ + qq) * HWN + hw];
    }

    #pragma unroll
    for (int mi = 0; mi < 6; mi++) {
        int m0 = warp_m * 96 + mi * 16 + g;
        int q0 = m0 % 3, q1 = (m0 + 8) % 3;
        float d0 = 0.f, d1 = 0.f;
        #pragma unroll
        for (int ni = 0; ni < 4; ni++) {
            int hw = hw0 + warp_n * 32 + ni * 8 + 2 * tg;
            float2 p0 = make_float2(acc[mi][ni][0], acc[mi][ni][1]);
            float2 p1 = make_float2(acc[mi][ni][2], acc[mi][ni][3]);
            *(float2*)&g_kv[((size_t)b * MM + m0    ) * HWN + hw] = p0;
            *(float2*)&g_kv[((size_t)b * MM + m0 + 8) * HWN + hw] = p1;
            float e0 = p0.x - qv[ni][q0].x, e1 = p0.y - qv[ni][q0].y;
            d0 += e0 * e0 + e1 * e1;
            float f0 = p1.x - qv[ni][q1].x, f1 = p1.y - qv[ni][q1].y;
            d1 += f0 * f0 + f1 * f1;
        }
        d0 += __shfl_xor_sync(0xffffffffu, d0, 1);
        d0 += __shfl_xor_sync(0xffffffffu, d0, 2);
        d1 += __shfl_xor_sync(0xffffffffu, d1, 1);
        d1 += __shfl_xor_sync(0xffffffffu, d1, 2);
        if (tg == 0) {
            sdist[m0][warp_n]     = d0;
            sdist[m0 + 8][warp_n] = d1;
        }
    }
    __syncthreads();
    if (tid < KC) {
        float s = 0.f;
        #pragma unroll
        for (int qq = 0; qq < 3; qq++)
            #pragma unroll
            for (int wn = 0; wn < 4; wn++)
                s += sdist[tid * 3 + qq][wn];
        g_part[((size_t)b * NT + blockIdx.x) * KC + tid] = s;
    }
}

// ============================================================================
// Pass 2: fixed-order tile sum + argmin (first-min tie-break)
// ============================================================================
__global__ void argmin_kernel(float* __restrict__ out_codes) {
    const int b = blockIdx.x;
    const int k = threadIdx.x;   // 64
    float s = 0.f;
    for (int tt = 0; tt < NT; tt++)
        s += g_part[(b * NT + tt) * KC + k];

    __shared__ float sv[KC];
    __shared__ int   si[KC];
    sv[k] = s; si[k] = k;
    __syncthreads();
    for (int off = 32; off > 0; off >>= 1) {
        if (k < off) {
            float ov = sv[k + off];
            int   oi = si[k + off];
            if (ov < sv[k] || (ov == sv[k] && oi < si[k])) { sv[k] = ov; si[k] = oi; }
        }
        __syncthreads();
    }
    if (k == 0) {
        g_code[b] = si[0];
        out_codes[b] = (float)si[0];
    }
}

// ============================================================================
// Pass 3: gather selected kv rows + loss partials (4-way hw split)
// ============================================================================
__global__ __launch_bounds__(256)
void gather_loss_kernel(const float* __restrict__ query,
                        float* __restrict__ out_sel) {
    const int blk = blockIdx.x;      // 0..95
    const int ch  = blockIdx.y;      // 0..3
    const int b   = blk / DQ;
    const int qq  = blk % DQ;
    const int tid = threadIdx.x;
    const int code = g_code[b];
    const int base = ch * 1024;

    const float* src = &g_kv[((size_t)b * MM + code * DQ + qq) * HWN + base];
    const float* qp  = &query[(size_t)(b * DQ + qq) * HWN + base];
    float*       dst = &out_sel[(size_t)(b * DQ + qq) * HWN + base];

    float s = 0.f;
    #pragma unroll
    for (int j = 0; j < 4; j++) {
        int i = tid + j * 256;
        float v = src[i];
        dst[i] = v;
        float d = v - qp[i];
        s += d * d;
    }
    __shared__ float red[256];
    red[tid] = s;
    __syncthreads();
    for (int off = 128; off > 0; off >>= 1) {
        if (tid < off) red[tid] += red[tid + off];
        __syncthreads();
    }
    if (tid == 0) g_loss[blk * 4 + ch] = red[0];
}

__global__ void loss_final_kernel(float* __restrict__ out_loss) {
    const int tid = threadIdx.x;     // 128
    float s = g_loss[tid] + g_loss[tid + 128] + g_loss[tid + 256];
    __shared__ float red[128];
    red[tid] = s;
    __syncthreads();
    for (int off = 64; off > 0; off >>= 1) {
        if (tid < off) red[tid] += red[tid + off];
        __syncthreads();
    }
    if (tid == 0) *out_loss = red[0] / (float)((size_t)BB * DQ * HWN);
}

// ============================================================================
extern "C" void kernel_launch(void* const* d_in, const int* in_sizes, int n_in,
                              void* d_out, int out_size) {
    const float* feat  = (const float*)d_in[0];
    const float* query = (const float*)d_in[1];
    const float* Wm    = (const float*)d_in[2];
    float* out = (float*)d_out;

    cudaFuncSetAttribute((const void*)kv_mma_kernel,
                         cudaFuncAttributeMaxDynamicSharedMemorySize, SMEM_TOT);

    wsplit_kernel<<<192, 256>>>(Wm);
    dim3 g1(NT, BB);
    kv_mma_kernel<<<g1, 256, SMEM_TOT>>>(feat, query);
    argmin_kernel<<<BB, KC>>>(out + (size_t)BB * DQ * HWN);
    dim3 g3(BB * DQ, 4);
    gather_loss_kernel<<<g3, 256>>>(query, out);
    loss_final_kernel<<<1, 128>>>(out + (size_t)BB * DQ * HWN + BB);
}

// round 5
// speedup vs baseline: 3.4948x; 1.1724x over previous
#include <cuda_runtime.h>
#include <cuda_fp16.h>
#include <cstdint>

#define BB   32
#define DIM  512
#define HWN  4096
#define KC   64
#define DQ   3
#define MM   192
#define NTILE 128           // hw per CTA
#define NT   32             // 4096/128
#define KSTAGE 32
#define NSTAGE 16           // 512/32

// dynamic smem layout
#define W_BUF_B   30720     // per buffer: hi 15360 (192*80) + lo 15360
#define OFF_W     0
#define OFF_F     61440     // fp32 feat stage: 2 x 16384  ([k32][n128] fp32)
#define OFF_BH    94208     // fp16 hi [k32][n128], swizzled, 8192
#define SMEM_TOT  102400

// ---------------- scratch ----------------
__device__ float    g_kv[(size_t)BB * MM * HWN];     // [b][m][hw]
__device__ float    g_part[BB * NT * KC];
__device__ int      g_code[BB];
__device__ float    g_loss[BB * DQ * 4];
__device__ unsigned g_Whi[MM * DIM / 2];             // f16x2, [m][kpair]
__device__ unsigned g_Wlo[MM * DIM / 2];

// ---------------- helpers ----------------
__device__ __forceinline__ uint32_t smem_u32(const void* p) {
    uint32_t a;
    asm("{ .reg .u64 t; cvta.to.shared.u64 t, %1; cvt.u32.u64 %0, t; }" : "=r"(a) : "l"(p));
    return a;
}
__device__ __forceinline__ void cp16(uint32_t smem, const void* gmem) {
    unsigned long long ga = (unsigned long long)__cvta_generic_to_global(gmem);
    asm volatile("cp.async.cg.shared.global [%0], [%1], 16;" :: "r"(smem), "l"(ga));
}
__device__ __forceinline__ void cp_commit() { asm volatile("cp.async.commit_group;"); }
__device__ __forceinline__ void cp_wait0() { asm volatile("cp.async.wait_group 0;" ::: "memory"); }

__device__ __forceinline__ void ldm4(unsigned* r, uint32_t a) {
    asm volatile("ldmatrix.sync.aligned.m8n8.x4.shared.b16 {%0,%1,%2,%3}, [%4];"
                 : "=r"(r[0]), "=r"(r[1]), "=r"(r[2]), "=r"(r[3]) : "r"(a));
}
__device__ __forceinline__ void ldm4t(unsigned* r, uint32_t a) {
    asm volatile("ldmatrix.sync.aligned.m8n8.x4.trans.shared.b16 {%0,%1,%2,%3}, [%4];"
                 : "=r"(r[0]), "=r"(r[1]), "=r"(r[2]), "=r"(r[3]) : "r"(a));
}
__device__ __forceinline__ void mma16816(float* c, const unsigned* a, const unsigned* b) {
    asm volatile("mma.sync.aligned.m16n8k16.row.col.f32.f16.f16.f32 "
                 "{%0,%1,%2,%3}, {%4,%5,%6,%7}, {%8,%9}, {%0,%1,%2,%3};"
                 : "+f"(c[0]), "+f"(c[1]), "+f"(c[2]), "+f"(c[3])
                 : "r"(a[0]), "r"(a[1]), "r"(a[2]), "r"(a[3]), "r"(b[0]), "r"(b[1]));
}
// pack fp16x2: {lo half = x0, hi half = x1}
__device__ __forceinline__ unsigned cvt2(float x0, float x1) {
    unsigned r;
    asm("cvt.rn.f16x2.f32 %0, %1, %2;" : "=r"(r) : "f"(x1), "f"(x0));
    return r;
}
__device__ __forceinline__ float lo_f32(unsigned r) {
    return __half2float(__ushort_as_half((unsigned short)(r & 0xffffu)));
}
__device__ __forceinline__ float hi_f32(unsigned r) {
    return __half2float(__ushort_as_half((unsigned short)(r >> 16)));
}

// ============================================================================
// Pass 0: split W fp32 -> fp16 hi/lo packed k-pairs
// ============================================================================
__global__ void wsplit_kernel(const float* __restrict__ W) {
    int i = blockIdx.x * 256 + threadIdx.x;
    if (i >= MM * DIM / 2) return;
    float x0 = W[2 * i], x1 = W[2 * i + 1];
    unsigned h = cvt2(x0, x1);
    g_Whi[i] = h;
    g_Wlo[i] = cvt2(x0 - lo_f32(h), x1 - hi_f32(h));
}

// ============================================================================
// Pass 1: C[m,hw] = W @ feat per batch via mma.sync fp16x2 (Wh+Wl vs Fh).
// 256 threads (8 warps: 2m x 4n). Cooperative fp16 conversion + ldmatrix.trans.
// ============================================================================
__global__ __launch_bounds__(256)
void kv_mma_kernel(const float* __restrict__ feat,
                   const float* __restrict__ query) {
    extern __shared__ __align__(16) unsigned char dyn[];
    __shared__ float sdist[MM][4];

    const int tid  = threadIdx.x;
    const int b    = blockIdx.y;
    const int hw0  = blockIdx.x * NTILE;
    const int lane = tid & 31, wid = tid >> 5;
    const int warp_m = wid >> 2;          // 0..1 -> m offset *96
    const int warp_n = wid & 3;           // 0..3 -> hw offset *32
    const int g  = lane >> 2, tg = lane & 3;

    const uint32_t sbase = smem_u32(dyn);

    auto issue = [&](int s, int buf) {
        const uint32_t fb = sbase + OFF_F + (uint32_t)buf * 16384;
        #pragma unroll
        for (int j = 0; j < 4; j++) {                // feat: 32 rows x 32 chunks
            int i = tid + j * 256;
            int kk = i >> 5, c = i & 31;
            cp16(fb + kk * 512 + c * 16,
                 feat + ((size_t)(b * DIM + s * KSTAGE + kk)) * HWN + hw0 + c * 4);
        }
        const uint32_t wb = sbase + OFF_W + (uint32_t)buf * W_BUF_B;
        #pragma unroll
        for (int j = 0; j < 3; j++) {                // W hi/lo: 192 rows x 4 chunks
            int i = tid + j * 256;
            int m = i >> 2, c = i & 3;
            cp16(wb + m * 80 + c * 16,         g_Whi + m * 256 + s * 16 + c * 4);
            cp16(wb + 15360 + m * 80 + c * 16, g_Wlo + m * 256 + s * 16 + c * 4);
        }
    };

    float acc[6][4][4];
    #pragma unroll
    for (int mi = 0; mi < 6; mi++)
        #pragma unroll
        for (int ni = 0; ni < 4; ni++)
            #pragma unroll
            for (int r = 0; r < 4; r++) acc[mi][ni][r] = 0.f;

    // B ldmatrix lane addressing
    const int b_r      = lane & 7;
    const int b_khalf  = (lane >> 3) & 1;
    const int b_nhalf  = (lane >> 4) & 1;
    const uint32_t b_ncol0 = (uint32_t)(warp_n * 32 + b_nhalf * 8);

    issue(0, 0); cp_commit();

    for (int s = 0; s < NSTAGE; s++) {
        const int buf = s & 1;
        cp_wait0();
        __syncthreads();

        // ---- cooperative fp32 -> fp16 (hi only) conversion ----
        {
            const float* fsrc = (const float*)(dyn + OFF_F + (size_t)buf * 16384);
            #pragma unroll
            for (int p = 0; p < 2; p++) {
                int k = wid * 4 + p * 2 + (lane >> 4);
                int l = lane & 15;
                float4 v0 = *(const float4*)(fsrc + k * 128 + l * 8);
                float4 v1 = *(const float4*)(fsrc + k * 128 + l * 8 + 4);
                unsigned h0 = cvt2(v0.x, v0.y), h1 = cvt2(v0.z, v0.w);
                unsigned h2 = cvt2(v1.x, v1.y), h3 = cvt2(v1.z, v1.w);
                uint32_t off = (uint32_t)(k * 256 + ((l * 16) ^ ((k & 7) << 4)));
                *(uint4*)(dyn + OFF_BH + off) = make_uint4(h0, h1, h2, h3);
            }
        }
        __syncthreads();

        if (s + 1 < NSTAGE) { issue(s + 1, buf ^ 1); cp_commit(); }

        const uint32_t wbh = sbase + OFF_W + (uint32_t)buf * W_BUF_B;
        const uint32_t wbl = wbh + 15360;

        #pragma unroll
        for (int ks = 0; ks < 2; ks++) {
            // ---- B fragments via ldmatrix.trans (hi only) ----
            unsigned bh[2][4];
            {
                uint32_t k = (uint32_t)(ks * 16 + b_khalf * 8 + b_r);
                uint32_t rowb = sbase + OFF_BH + k * 256;
                uint32_t sw = (uint32_t)(b_r << 4);
                #pragma unroll
                for (int half = 0; half < 2; half++) {
                    uint32_t coff = (((b_ncol0 + half * 16) * 2) ^ sw);
                    ldm4t(bh[half], rowb + coff);
                }
            }
            // ---- A frags per m-tile + 2-pass mma (dep distance 4) ----
            #pragma unroll
            for (int mi = 0; mi < 6; mi++) {
                uint32_t aoff = (uint32_t)(warp_m * 96 + mi * 16 + (lane & 15)) * 80
                              + ks * 32 + (lane >> 4) * 16;
                unsigned ah[4], al[4];
                ldm4(ah, wbh + aoff);
                ldm4(al, wbl + aoff);
                #pragma unroll
                for (int ni = 0; ni < 4; ni++)
                    mma16816(acc[mi][ni], ah, &bh[ni >> 1][(ni & 1) * 2]);
                #pragma unroll
                for (int ni = 0; ni < 4; ni++)
                    mma16816(acc[mi][ni], al, &bh[ni >> 1][(ni & 1) * 2]);
            }
        }
        __syncthreads();
    }

    // ---- epilogue: write kv + fixed-order distance partials ----
    float2 qv[4][3];
    #pragma unroll
    for (int ni = 0; ni < 4; ni++) {
        int hw = hw0 + warp_n * 32 + ni * 8 + 2 * tg;
        #pragma unroll
        for (int qq = 0; qq < 3; qq++)
            qv[ni][qq] = *(const float2*)&query[((size_t)b * DQ + qq) * HWN + hw];
    }

    #pragma unroll
    for (int mi = 0; mi < 6; mi++) {
        int m0 = warp_m * 96 + mi * 16 + g;
        int q0 = m0 % 3, q1 = (m0 + 8) % 3;
        float d0 = 0.f, d1 = 0.f;
        #pragma unroll
        for (int ni = 0; ni < 4; ni++) {
            int hw = hw0 + warp_n * 32 + ni * 8 + 2 * tg;
            float2 p0 = make_float2(acc[mi][ni][0], acc[mi][ni][1]);
            float2 p1 = make_float2(acc[mi][ni][2], acc[mi][ni][3]);
            *(float2*)&g_kv[((size_t)b * MM + m0    ) * HWN + hw] = p0;
            *(float2*)&g_kv[((size_t)b * MM + m0 + 8) * HWN + hw] = p1;
            float e0 = p0.x - qv[ni][q0].x, e1 = p0.y - qv[ni][q0].y;
            d0 += e0 * e0 + e1 * e1;
            float f0 = p1.x - qv[ni][q1].x, f1 = p1.y - qv[ni][q1].y;
            d1 += f0 * f0 + f1 * f1;
        }
        d0 += __shfl_xor_sync(0xffffffffu, d0, 1);
        d0 += __shfl_xor_sync(0xffffffffu, d0, 2);
        d1 += __shfl_xor_sync(0xffffffffu, d1, 1);
        d1 += __shfl_xor_sync(0xffffffffu, d1, 2);
        if (tg == 0) {
            sdist[m0][warp_n]     = d0;
            sdist[m0 + 8][warp_n] = d1;
        }
    }
    __syncthreads();
    if (tid < KC) {
        float s = 0.f;
        #pragma unroll
        for (int qq = 0; qq < 3; qq++)
            #pragma unroll
            for (int wn = 0; wn < 4; wn++)
                s += sdist[tid * 3 + qq][wn];
        g_part[((size_t)b * NT + blockIdx.x) * KC + tid] = s;
    }
}

// ============================================================================
// Pass 2: fixed-order tile sum + argmin (first-min tie-break)
// ============================================================================
__global__ void argmin_kernel(float* __restrict__ out_codes) {
    const int b = blockIdx.x;
    const int k = threadIdx.x;   // 64
    float s = 0.f;
    for (int tt = 0; tt < NT; tt++)
        s += g_part[(b * NT + tt) * KC + k];

    __shared__ float sv[KC];
    __shared__ int   si[KC];
    sv[k] = s; si[k] = k;
    __syncthreads();
    for (int off = 32; off > 0; off >>= 1) {
        if (k < off) {
            float ov = sv[k + off];
            int   oi = si[k + off];
            if (ov < sv[k] || (ov == sv[k] && oi < si[k])) { sv[k] = ov; si[k] = oi; }
        }
        __syncthreads();
    }
    if (k == 0) {
        g_code[b] = si[0];
        out_codes[b] = (float)si[0];
    }
}

// ============================================================================
// Pass 3: gather selected kv rows + loss partials (4-way hw split)
// ============================================================================
__global__ __launch_bounds__(256)
void gather_loss_kernel(const float* __restrict__ query,
                        float* __restrict__ out_sel) {
    const int blk = blockIdx.x;      // 0..95
    const int ch  = blockIdx.y;      // 0..3
    const int b   = blk / DQ;
    const int qq  = blk % DQ;
    const int tid = threadIdx.x;
    const int code = g_code[b];
    const int base = ch * 1024;

    const float* src = &g_kv[((size_t)b * MM + code * DQ + qq) * HWN + base];
    const float* qp  = &query[(size_t)(b * DQ + qq) * HWN + base];
    float*       dst = &out_sel[(size_t)(b * DQ + qq) * HWN + base];

    float s = 0.f;
    #pragma unroll
    for (int j = 0; j < 4; j++) {
        int i = tid + j * 256;
        float v = src[i];
        dst[i] = v;
        float d = v - qp[i];
        s += d * d;
    }
    __shared__ float red[256];
    red[tid] = s;
    __syncthreads();
    for (int off = 128; off > 0; off >>= 1) {
        if (tid < off) red[tid] += red[tid + off];
        __syncthreads();
    }
    if (tid == 0) g_loss[blk * 4 + ch] = red[0];
}

__global__ void loss_final_kernel(float* __restrict__ out_loss) {
    const int tid = threadIdx.x;     // 128
    float s = g_loss[tid] + g_loss[tid + 128] + g_loss[tid + 256];
    __shared__ float red[128];
    red[tid] = s;
    __syncthreads();
    for (int off = 64; off > 0; off >>= 1) {
        if (tid < off) red[tid] += red[tid + off];
        __syncthreads();
    }
    if (tid == 0) *out_loss = red[0] / (float)((size_t)BB * DQ * HWN);
}

// ============================================================================
extern "C" void kernel_launch(void* const* d_in, const int* in_sizes, int n_in,
                              void* d_out, int out_size) {
    const float* feat  = (const float*)d_in[0];
    const float* query = (const float*)d_in[1];
    const float* Wm    = (const float*)d_in[2];
    float* out = (float*)d_out;

    cudaFuncSetAttribute((const void*)kv_mma_kernel,
                         cudaFuncAttributeMaxDynamicSharedMemorySize, SMEM_TOT);

    wsplit_kernel<<<192, 256>>>(Wm);
    dim3 g1(NT, BB);
    kv_mma_kernel<<<g1, 256, SMEM_TOT>>>(feat, query);
    argmin_kernel<<<BB, KC>>>(out + (size_t)BB * DQ * HWN);
    dim3 g3(BB * DQ, 4);
    gather_loss_kernel<<<g3, 256>>>(query, out);
    loss_final_kernel<<<1, 128>>>(out + (size_t)BB * DQ * HWN + BB);
}

// round 6
// speedup vs baseline: 3.5978x; 1.0295x over previous
#include <cuda_runtime.h>
#include <cuda_fp16.h>
#include <cstdint>

#define BB   32
#define DIM  512
#define HWN  4096
#define KC   64
#define DQ   3
#define MM   192
#define NTILE 128           // hw per CTA
#define NT   32             // 4096/128
#define KSTAGE 32
#define NSTAGE 16           // 512/32

// dynamic smem layout
#define W_BUF_B   30720     // per buffer: hi 15360 (192*80) + lo 15360
#define OFF_W     0
#define OFF_BH    61440     // fp16 feat [k32][n128] swizzled, 2 x 8192
#define SMEM_TOT  77824

// ---------------- scratch ----------------
__device__ float    g_kv[(size_t)BB * MM * HWN];     // [b][m][hw]
__device__ float    g_part[BB * NT * KC];
__device__ int      g_code[BB];
__device__ float    g_loss[BB * DQ * 4];
__device__ unsigned g_Whi[MM * DIM / 2];             // f16x2, [m][kpair]
__device__ unsigned g_Wlo[MM * DIM / 2];

// ---------------- helpers ----------------
__device__ __forceinline__ uint32_t smem_u32(const void* p) {
    uint32_t a;
    asm("{ .reg .u64 t; cvta.to.shared.u64 t, %1; cvt.u32.u64 %0, t; }" : "=r"(a) : "l"(p));
    return a;
}
__device__ __forceinline__ void cp16(uint32_t smem, const void* gmem) {
    unsigned long long ga = (unsigned long long)__cvta_generic_to_global(gmem);
    asm volatile("cp.async.cg.shared.global [%0], [%1], 16;" :: "r"(smem), "l"(ga));
}
__device__ __forceinline__ void cp_commit() { asm volatile("cp.async.commit_group;"); }
__device__ __forceinline__ void cp_wait0() { asm volatile("cp.async.wait_group 0;" ::: "memory"); }

__device__ __forceinline__ void ldm4(unsigned* r, uint32_t a) {
    asm volatile("ldmatrix.sync.aligned.m8n8.x4.shared.b16 {%0,%1,%2,%3}, [%4];"
                 : "=r"(r[0]), "=r"(r[1]), "=r"(r[2]), "=r"(r[3]) : "r"(a));
}
__device__ __forceinline__ void ldm4t(unsigned* r, uint32_t a) {
    asm volatile("ldmatrix.sync.aligned.m8n8.x4.trans.shared.b16 {%0,%1,%2,%3}, [%4];"
                 : "=r"(r[0]), "=r"(r[1]), "=r"(r[2]), "=r"(r[3]) : "r"(a));
}
__device__ __forceinline__ void mma16816(float* c, const unsigned* a, const unsigned* b) {
    asm volatile("mma.sync.aligned.m16n8k16.row.col.f32.f16.f16.f32 "
                 "{%0,%1,%2,%3}, {%4,%5,%6,%7}, {%8,%9}, {%0,%1,%2,%3};"
                 : "+f"(c[0]), "+f"(c[1]), "+f"(c[2]), "+f"(c[3])
                 : "r"(a[0]), "r"(a[1]), "r"(a[2]), "r"(a[3]), "r"(b[0]), "r"(b[1]));
}
// pack fp16x2: {lo half = x0, hi half = x1}
__device__ __forceinline__ unsigned cvt2(float x0, float x1) {
    unsigned r;
    asm("cvt.rn.f16x2.f32 %0, %1, %2;" : "=r"(r) : "f"(x1), "f"(x0));
    return r;
}
__device__ __forceinline__ float lo_f32(unsigned r) {
    return __half2float(__ushort_as_half((unsigned short)(r & 0xffffu)));
}
__device__ __forceinline__ float hi_f32(unsigned r) {
    return __half2float(__ushort_as_half((unsigned short)(r >> 16)));
}

// ============================================================================
// Pass 0: split W fp32 -> fp16 hi/lo packed k-pairs
// ============================================================================
__global__ void wsplit_kernel(const float* __restrict__ W) {
    int i = blockIdx.x * 256 + threadIdx.x;
    if (i >= MM * DIM / 2) return;
    float x0 = W[2 * i], x1 = W[2 * i + 1];
    unsigned h = cvt2(x0, x1);
    g_Whi[i] = h;
    g_Wlo[i] = cvt2(x0 - lo_f32(h), x1 - hi_f32(h));
}

// ============================================================================
// Pass 1: C[m,hw] = W @ feat per batch via mma.sync fp16x2 (Wh+Wl vs Fh).
// 256 threads, 8 warps = 4m x 2n (warp tile m48 x n64). Feat: direct
// LDG -> cvt -> STS (no fp32 staging), double-buffered fp16 B, 1 sync/stage.
// ============================================================================
__global__ __launch_bounds__(256)
void kv_mma_kernel(const float* __restrict__ feat,
                   const float* __restrict__ query) {
    extern __shared__ __align__(16) unsigned char dyn[];
    __shared__ float sdist[MM][2];

    const int tid  = threadIdx.x;
    const int b    = blockIdx.y;
    const int hw0  = blockIdx.x * NTILE;
    const int lane = tid & 31, wid = tid >> 5;
    const int warp_m = wid >> 1;          // 0..3 -> m offset *48
    const int warp_n = wid & 1;           // 0..1 -> hw offset *64
    const int g  = lane >> 2, tg = lane & 3;

    const uint32_t sbase = smem_u32(dyn);

    // feat conversion addressing: thread covers k=ck, n=[cn, cn+16)
    const int ck = tid >> 3;
    const int cn = (tid & 7) * 16;
    const uint32_t sts0 = (uint32_t)(ck * 256 + (((cn * 2)     ) ^ ((ck & 7) << 4)));
    const uint32_t sts1 = (uint32_t)(ck * 256 + (((cn * 2) + 16) ^ ((ck & 7) << 4)));

    auto issueW = [&](int s, int buf) {
        const uint32_t wb = sbase + OFF_W + (uint32_t)buf * W_BUF_B;
        #pragma unroll
        for (int j = 0; j < 3; j++) {                // W hi/lo: 192 rows x 4 chunks
            int i = tid + j * 256;
            int m = i >> 2, c = i & 3;
            cp16(wb + m * 80 + c * 16,         g_Whi + m * 256 + s * 16 + c * 4);
            cp16(wb + 15360 + m * 80 + c * 16, g_Wlo + m * 256 + s * 16 + c * 4);
        }
    };

    float acc[3][8][4];
    #pragma unroll
    for (int mi = 0; mi < 3; mi++)
        #pragma unroll
        for (int ni = 0; ni < 8; ni++)
            #pragma unroll
            for (int r = 0; r < 4; r++) acc[mi][ni][r] = 0.f;

    // B ldmatrix lane addressing
    const int b_r      = lane & 7;
    const int b_khalf  = (lane >> 3) & 1;
    const int b_nhalf  = (lane >> 4) & 1;
    const uint32_t b_sw = (uint32_t)(b_r << 4);
    const uint32_t b_n0 = (uint32_t)(warp_n * 64 + b_nhalf * 8);

    // prefetch feat stage 0
    float4 f0, f1, f2, f3;
    {
        const float* fp = feat + ((size_t)(b * DIM + ck)) * HWN + hw0 + cn;
        f0 = *(const float4*)(fp);
        f1 = *(const float4*)(fp + 4);
        f2 = *(const float4*)(fp + 8);
        f3 = *(const float4*)(fp + 12);
    }
    issueW(0, 0); cp_commit();

    for (int s = 0; s < NSTAGE; s++) {
        const int buf = s & 1;
        const uint32_t bhb = sbase + OFF_BH + (uint32_t)buf * 8192;

        // ---- convert this stage's feat regs -> fp16 smem ----
        {
            unsigned h0 = cvt2(f0.x, f0.y), h1 = cvt2(f0.z, f0.w);
            unsigned h2 = cvt2(f1.x, f1.y), h3 = cvt2(f1.z, f1.w);
            unsigned h4 = cvt2(f2.x, f2.y), h5 = cvt2(f2.z, f2.w);
            unsigned h6 = cvt2(f3.x, f3.y), h7 = cvt2(f3.z, f3.w);
            *(uint4*)(dyn + OFF_BH + buf * 8192 + sts0) = make_uint4(h0, h1, h2, h3);
            *(uint4*)(dyn + OFF_BH + buf * 8192 + sts1) = make_uint4(h4, h5, h6, h7);
        }
        // ---- prefetch feat for next stage ----
        if (s + 1 < NSTAGE) {
            const float* fp = feat + ((size_t)(b * DIM + (s + 1) * KSTAGE + ck)) * HWN + hw0 + cn;
            f0 = *(const float4*)(fp);
            f1 = *(const float4*)(fp + 4);
            f2 = *(const float4*)(fp + 8);
            f3 = *(const float4*)(fp + 12);
        }
        cp_wait0();          // W for stage s landed
        __syncthreads();     // BH[buf] + W[buf] visible; stage s-1 reads done
        if (s + 1 < NSTAGE) { issueW(s + 1, buf ^ 1); cp_commit(); }

        const uint32_t wbh = sbase + OFF_W + (uint32_t)buf * W_BUF_B;
        const uint32_t wbl = wbh + 15360;

        #pragma unroll
        for (int ks = 0; ks < 2; ks++) {
            // ---- B fragments via ldmatrix.trans: 4 quarters of n64 ----
            unsigned bh[4][4];
            {
                uint32_t k = (uint32_t)(ks * 16 + b_khalf * 8 + b_r);
                uint32_t rowb = bhb + k * 256;
                #pragma unroll
                for (int q = 0; q < 4; q++) {
                    uint32_t coff = (((b_n0 + q * 16) * 2) ^ b_sw);
                    ldm4t(bh[q], rowb + coff);
                }
            }
            // ---- A frags per m-tile + 2-pass mma ----
            #pragma unroll
            for (int mi = 0; mi < 3; mi++) {
                uint32_t aoff = (uint32_t)(warp_m * 48 + mi * 16 + (lane & 15)) * 80
                              + ks * 32 + (lane >> 4) * 16;
                unsigned ah[4], al[4];
                ldm4(ah, wbh + aoff);
                ldm4(al, wbl + aoff);
                #pragma unroll
                for (int ni = 0; ni < 8; ni++)
                    mma16816(acc[mi][ni], ah, &bh[ni >> 1][(ni & 1) * 2]);
                #pragma unroll
                for (int ni = 0; ni < 8; ni++)
                    mma16816(acc[mi][ni], al, &bh[ni >> 1][(ni & 1) * 2]);
            }
        }
        __syncthreads();
    }

    // ---- epilogue: write kv + fixed-order distance partials ----
    float2 qv[8][3];
    #pragma unroll
    for (int ni = 0; ni < 8; ni++) {
        int hw = hw0 + warp_n * 64 + ni * 8 + 2 * tg;
        #pragma unroll
        for (int qq = 0; qq < 3; qq++)
            qv[ni][qq] = *(const float2*)&query[((size_t)b * DQ + qq) * HWN + hw];
    }

    #pragma unroll
    for (int mi = 0; mi < 3; mi++) {
        int m0 = warp_m * 48 + mi * 16 + g;
        int q0 = m0 % 3, q1 = (m0 + 8) % 3;
        float d0 = 0.f, d1 = 0.f;
        #pragma unroll
        for (int ni = 0; ni < 8; ni++) {
            int hw = hw0 + warp_n * 64 + ni * 8 + 2 * tg;
            float2 p0 = make_float2(acc[mi][ni][0], acc[mi][ni][1]);
            float2 p1 = make_float2(acc[mi][ni][2], acc[mi][ni][3]);
            *(float2*)&g_kv[((size_t)b * MM + m0    ) * HWN + hw] = p0;
            *(float2*)&g_kv[((size_t)b * MM + m0 + 8) * HWN + hw] = p1;
            float e0 = p0.x - qv[ni][q0].x, e1 = p0.y - qv[ni][q0].y;
            d0 += e0 * e0 + e1 * e1;
            float f0e = p1.x - qv[ni][q1].x, f1e = p1.y - qv[ni][q1].y;
            d1 += f0e * f0e + f1e * f1e;
        }
        d0 += __shfl_xor_sync(0xffffffffu, d0, 1);
        d0 += __shfl_xor_sync(0xffffffffu, d0, 2);
        d1 += __shfl_xor_sync(0xffffffffu, d1, 1);
        d1 += __shfl_xor_sync(0xffffffffu, d1, 2);
        if (tg == 0) {
            sdist[m0][warp_n]     = d0;
            sdist[m0 + 8][warp_n] = d1;
        }
    }
    __syncthreads();
    if (tid < KC) {
        float s = 0.f;
        #pragma unroll
        for (int qq = 0; qq < 3; qq++)
            s += sdist[tid * 3 + qq][0] + sdist[tid * 3 + qq][1];
        g_part[((size_t)b * NT + blockIdx.x) * KC + tid] = s;
    }
}

// ============================================================================
// Pass 2: fixed-order tile sum + argmin (first-min tie-break)
// ============================================================================
__global__ void argmin_kernel(float* __restrict__ out_codes) {
    const int b = blockIdx.x;
    const int k = threadIdx.x;   // 64
    float s = 0.f;
    for (int tt = 0; tt < NT; tt++)
        s += g_part[(b * NT + tt) * KC + k];

    __shared__ float sv[KC];
    __shared__ int   si[KC];
    sv[k] = s; si[k] = k;
    __syncthreads();
    for (int off = 32; off > 0; off >>= 1) {
        if (k < off) {
            float ov = sv[k + off];
            int   oi = si[k + off];
            if (ov < sv[k] || (ov == sv[k] && oi < si[k])) { sv[k] = ov; si[k] = oi; }
        }
        __syncthreads();
    }
    if (k == 0) {
        g_code[b] = si[0];
        out_codes[b] = (float)si[0];
    }
}

// ============================================================================
// Pass 3: gather selected kv rows + loss partials (4-way hw split)
// ============================================================================
__global__ __launch_bounds__(256)
void gather_loss_kernel(const float* __restrict__ query,
                        float* __restrict__ out_sel) {
    const int blk = blockIdx.x;      // 0..95
    const int ch  = blockIdx.y;      // 0..3
    const int b   = blk / DQ;
    const int qq  = blk % DQ;
    const int tid = threadIdx.x;
    const int code = g_code[b];
    const int base = ch * 1024;

    const float* src = &g_kv[((size_t)b * MM + code * DQ + qq) * HWN + base];
    const float* qp  = &query[(size_t)(b * DQ + qq) * HWN + base];
    float*       dst = &out_sel[(size_t)(b * DQ + qq) * HWN + base];

    float s = 0.f;
    #pragma unroll
    for (int j = 0; j < 4; j++) {
        int i = tid + j * 256;
        float v = src[i];
        dst[i] = v;
        float d = v - qp[i];
        s += d * d;
    }
    __shared__ float red[256];
    red[tid] = s;
    __syncthreads();
    for (int off = 128; off > 0; off >>= 1) {
        if (tid < off) red[tid] += red[tid + off];
        __syncthreads();
    }
    if (tid == 0) g_loss[blk * 4 + ch] = red[0];
}

__global__ void loss_final_kernel(float* __restrict__ out_loss) {
    const int tid = threadIdx.x;     // 128
    float s = g_loss[tid] + g_loss[tid + 128] + g_loss[tid + 256];
    __shared__ float red[128];
    red[tid] = s;
    __syncthreads();
    for (int off = 64; off > 0; off >>= 1) {
        if (tid < off) red[tid] += red[tid + off];
        __syncthreads();
    }
    if (tid == 0) *out_loss = red[0] / (float)((size_t)BB * DQ * HWN);
}

// ============================================================================
extern "C" void kernel_launch(void* const* d_in, const int* in_sizes, int n_in,
                              void* d_out, int out_size) {
    const float* feat  = (const float*)d_in[0];
    const float* query = (const float*)d_in[1];
    const float* Wm    = (const float*)d_in[2];
    float* out = (float*)d_out;

    cudaFuncSetAttribute((const void*)kv_mma_kernel,
                         cudaFuncAttributeMaxDynamicSharedMemorySize, SMEM_TOT);

    wsplit_kernel<<<192, 256>>>(Wm);
    dim3 g1(NT, BB);
    kv_mma_kernel<<<g1, 256, SMEM_TOT>>>(feat, query);
    argmin_kernel<<<BB, KC>>>(out + (size_t)BB * DQ * HWN);
    dim3 g3(BB * DQ, 4);
    gather_loss_kernel<<<g3, 256>>>(query, out);
    loss_final_kernel<<<1, 128>>>(out + (size_t)BB * DQ * HWN + BB);
}

// round 7
// speedup vs baseline: 5.1122x; 1.4209x over previous
#include <cuda_runtime.h>
#include <cuda_fp16.h>
#include <cstdint>

#define BB   32
#define DIM  512
#define HWN  4096
#define KC   64
#define DQ   3
#define MM   192
#define NTILE 128           // hw per CTA
#define NT   32             // 4096/128
#define KSTAGE 32
#define NSTAGE 16           // 512/32

// dynamic smem layout
#define W_BUF_B   15360     // per buffer: hi only (192*80)
#define OFF_W     0
#define OFF_BH    30720     // fp16 feat [k32][n128] swizzled, 2 x 8192
#define SMEM_TOT  47104

// ---------------- scratch ----------------
__device__ float    g_kv[(size_t)BB * MM * HWN];     // [b][m][hw]
__device__ float    g_part[BB * NT * KC];
__device__ int      g_code[BB];
__device__ float    g_loss[BB * DQ * 4];
__device__ unsigned g_Whi[MM * DIM / 2];             // f16x2, [m][kpair]

// ---------------- helpers ----------------
__device__ __forceinline__ uint32_t smem_u32(const void* p) {
    uint32_t a;
    asm("{ .reg .u64 t; cvta.to.shared.u64 t, %1; cvt.u32.u64 %0, t; }" : "=r"(a) : "l"(p));
    return a;
}
__device__ __forceinline__ void cp16(uint32_t smem, const void* gmem) {
    unsigned long long ga = (unsigned long long)__cvta_generic_to_global(gmem);
    asm volatile("cp.async.cg.shared.global [%0], [%1], 16;" :: "r"(smem), "l"(ga));
}
__device__ __forceinline__ void cp_commit() { asm volatile("cp.async.commit_group;"); }
__device__ __forceinline__ void cp_wait0() { asm volatile("cp.async.wait_group 0;" ::: "memory"); }

__device__ __forceinline__ void ldm4(unsigned* r, uint32_t a) {
    asm volatile("ldmatrix.sync.aligned.m8n8.x4.shared.b16 {%0,%1,%2,%3}, [%4];"
                 : "=r"(r[0]), "=r"(r[1]), "=r"(r[2]), "=r"(r[3]) : "r"(a));
}
__device__ __forceinline__ void ldm4t(unsigned* r, uint32_t a) {
    asm volatile("ldmatrix.sync.aligned.m8n8.x4.trans.shared.b16 {%0,%1,%2,%3}, [%4];"
                 : "=r"(r[0]), "=r"(r[1]), "=r"(r[2]), "=r"(r[3]) : "r"(a));
}
__device__ __forceinline__ void mma16816(float* c, const unsigned* a, const unsigned* b) {
    asm volatile("mma.sync.aligned.m16n8k16.row.col.f32.f16.f16.f32 "
                 "{%0,%1,%2,%3}, {%4,%5,%6,%7}, {%8,%9}, {%0,%1,%2,%3};"
                 : "+f"(c[0]), "+f"(c[1]), "+f"(c[2]), "+f"(c[3])
                 : "r"(a[0]), "r"(a[1]), "r"(a[2]), "r"(a[3]), "r"(b[0]), "r"(b[1]));
}
// pack fp16x2: {lo half = x0, hi half = x1}
__device__ __forceinline__ unsigned cvt2(float x0, float x1) {
    unsigned r;
    asm("cvt.rn.f16x2.f32 %0, %1, %2;" : "=r"(r) : "f"(x1), "f"(x0));
    return r;
}

// ============================================================================
// Pass 0: W fp32 -> fp16 packed k-pairs (hi only)
// ============================================================================
__global__ void wsplit_kernel(const float* __restrict__ W) {
    int i = blockIdx.x * 256 + threadIdx.x;
    if (i >= MM * DIM / 2) return;
    g_Whi[i] = cvt2(W[2 * i], W[2 * i + 1]);
}

// ============================================================================
// Pass 1: C[m,hw] = W @ feat per batch via single-pass fp16 mma.sync.
// 256 threads, 8 warps = 4m x 2n (warp tile m48 x n64). Feat: direct
// LDG -> cvt -> STS, double-buffered fp16 B + W, 1 sync/stage.
// ============================================================================
__global__ __launch_bounds__(256)
void kv_mma_kernel(const float* __restrict__ feat,
                   const float* __restrict__ query) {
    extern __shared__ __align__(16) unsigned char dyn[];
    __shared__ float sdist[MM][2];

    const int tid  = threadIdx.x;
    const int b    = blockIdx.y;
    const int hw0  = blockIdx.x * NTILE;
    const int lane = tid & 31, wid = tid >> 5;
    const int warp_m = wid >> 1;          // 0..3 -> m offset *48
    const int warp_n = wid & 1;           // 0..1 -> hw offset *64
    const int g  = lane >> 2, tg = lane & 3;

    const uint32_t sbase = smem_u32(dyn);

    // feat conversion addressing: thread covers k=ck, n=[cn, cn+16)
    const int ck = tid >> 3;
    const int cn = (tid & 7) * 16;
    const uint32_t sts0 = (uint32_t)(ck * 256 + (((cn * 2)     ) ^ ((ck & 7) << 4)));
    const uint32_t sts1 = (uint32_t)(ck * 256 + (((cn * 2) + 16) ^ ((ck & 7) << 4)));

    auto issueW = [&](int s, int buf) {
        const uint32_t wb = sbase + OFF_W + (uint32_t)buf * W_BUF_B;
        #pragma unroll
        for (int j = 0; j < 3; j++) {                // W hi: 192 rows x 4 chunks
            int i = tid + j * 256;
            int m = i >> 2, c = i & 3;
            cp16(wb + m * 80 + c * 16, g_Whi + m * 256 + s * 16 + c * 4);
        }
    };

    float acc[3][8][4];
    #pragma unroll
    for (int mi = 0; mi < 3; mi++)
        #pragma unroll
        for (int ni = 0; ni < 8; ni++)
            #pragma unroll
            for (int r = 0; r < 4; r++) acc[mi][ni][r] = 0.f;

    // B ldmatrix lane addressing
    const int b_r      = lane & 7;
    const int b_khalf  = (lane >> 3) & 1;
    const int b_nhalf  = (lane >> 4) & 1;
    const uint32_t b_sw = (uint32_t)(b_r << 4);
    const uint32_t b_n0 = (uint32_t)(warp_n * 64 + b_nhalf * 8);

    // prefetch feat stage 0
    float4 f0, f1, f2, f3;
    {
        const float* fp = feat + ((size_t)(b * DIM + ck)) * HWN + hw0 + cn;
        f0 = *(const float4*)(fp);
        f1 = *(const float4*)(fp + 4);
        f2 = *(const float4*)(fp + 8);
        f3 = *(const float4*)(fp + 12);
    }
    issueW(0, 0); cp_commit();

    for (int s = 0; s < NSTAGE; s++) {
        const int buf = s & 1;
        const uint32_t bhb = sbase + OFF_BH + (uint32_t)buf * 8192;

        // ---- convert this stage's feat regs -> fp16 smem ----
        {
            unsigned h0 = cvt2(f0.x, f0.y), h1 = cvt2(f0.z, f0.w);
            unsigned h2 = cvt2(f1.x, f1.y), h3 = cvt2(f1.z, f1.w);
            unsigned h4 = cvt2(f2.x, f2.y), h5 = cvt2(f2.z, f2.w);
            unsigned h6 = cvt2(f3.x, f3.y), h7 = cvt2(f3.z, f3.w);
            *(uint4*)(dyn + OFF_BH + buf * 8192 + sts0) = make_uint4(h0, h1, h2, h3);
            *(uint4*)(dyn + OFF_BH + buf * 8192 + sts1) = make_uint4(h4, h5, h6, h7);
        }
        // ---- prefetch feat for next stage ----
        if (s + 1 < NSTAGE) {
            const float* fp = feat + ((size_t)(b * DIM + (s + 1) * KSTAGE + ck)) * HWN + hw0 + cn;
            f0 = *(const float4*)(fp);
            f1 = *(const float4*)(fp + 4);
            f2 = *(const float4*)(fp + 8);
            f3 = *(const float4*)(fp + 12);
        }
        cp_wait0();          // W for stage s landed
        __syncthreads();     // BH[buf] + W[buf] visible; stage s-1 reads done
        if (s + 1 < NSTAGE) { issueW(s + 1, buf ^ 1); cp_commit(); }

        const uint32_t wbh = sbase + OFF_W + (uint32_t)buf * W_BUF_B;

        #pragma unroll
        for (int ks = 0; ks < 2; ks++) {
            // ---- B fragments via ldmatrix.trans: 4 quarters of n64 ----
            unsigned bh[4][4];
            {
                uint32_t k = (uint32_t)(ks * 16 + b_khalf * 8 + b_r);
                uint32_t rowb = bhb + k * 256;
                #pragma unroll
                for (int q = 0; q < 4; q++) {
                    uint32_t coff = (((b_n0 + q * 16) * 2) ^ b_sw);
                    ldm4t(bh[q], rowb + coff);
                }
            }
            // ---- A frags per m-tile + single-pass mma ----
            #pragma unroll
            for (int mi = 0; mi < 3; mi++) {
                uint32_t aoff = (uint32_t)(warp_m * 48 + mi * 16 + (lane & 15)) * 80
                              + ks * 32 + (lane >> 4) * 16;
                unsigned ah[4];
                ldm4(ah, wbh + aoff);
                #pragma unroll
                for (int ni = 0; ni < 8; ni++)
                    mma16816(acc[mi][ni], ah, &bh[ni >> 1][(ni & 1) * 2]);
            }
        }
        __syncthreads();
    }

    // ---- epilogue: write kv + fixed-order distance partials ----
    float2 qv[8][3];
    #pragma unroll
    for (int ni = 0; ni < 8; ni++) {
        int hw = hw0 + warp_n * 64 + ni * 8 + 2 * tg;
        #pragma unroll
        for (int qq = 0; qq < 3; qq++)
            qv[ni][qq] = *(const float2*)&query[((size_t)b * DQ + qq) * HWN + hw];
    }

    #pragma unroll
    for (int mi = 0; mi < 3; mi++) {
        int m0 = warp_m * 48 + mi * 16 + g;
        int q0 = m0 % 3, q1 = (m0 + 8) % 3;
        float d0 = 0.f, d1 = 0.f;
        #pragma unroll
        for (int ni = 0; ni < 8; ni++) {
            int hw = hw0 + warp_n * 64 + ni * 8 + 2 * tg;
            float2 p0 = make_float2(acc[mi][ni][0], acc[mi][ni][1]);
            float2 p1 = make_float2(acc[mi][ni][2], acc[mi][ni][3]);
            *(float2*)&g_kv[((size_t)b * MM + m0    ) * HWN + hw] = p0;
            *(float2*)&g_kv[((size_t)b * MM + m0 + 8) * HWN + hw] = p1;
            float e0 = p0.x - qv[ni][q0].x, e1 = p0.y - qv[ni][q0].y;
            d0 += e0 * e0 + e1 * e1;
            float f0e = p1.x - qv[ni][q1].x, f1e = p1.y - qv[ni][q1].y;
            d1 += f0e * f0e + f1e * f1e;
        }
        d0 += __shfl_xor_sync(0xffffffffu, d0, 1);
        d0 += __shfl_xor_sync(0xffffffffu, d0, 2);
        d1 += __shfl_xor_sync(0xffffffffu, d1, 1);
        d1 += __shfl_xor_sync(0xffffffffu, d1, 2);
        if (tg == 0) {
            sdist[m0][warp_n]     = d0;
            sdist[m0 + 8][warp_n] = d1;
        }
    }
    __syncthreads();
    if (tid < KC) {
        float s = 0.f;
        #pragma unroll
        for (int qq = 0; qq < 3; qq++)
            s += sdist[tid * 3 + qq][0] + sdist[tid * 3 + qq][1];
        g_part[((size_t)b * NT + blockIdx.x) * KC + tid] = s;
    }
}

// ============================================================================
// Pass 2: fixed-order tile sum + argmin (first-min tie-break)
// ============================================================================
__global__ void argmin_kernel(float* __restrict__ out_codes) {
    const int b = blockIdx.x;
    const int k = threadIdx.x;   // 64
    float s = 0.f;
    for (int tt = 0; tt < NT; tt++)
        s += g_part[(b * NT + tt) * KC + k];

    __shared__ float sv[KC];
    __shared__ int   si[KC];
    sv[k] = s; si[k] = k;
    __syncthreads();
    for (int off = 32; off > 0; off >>= 1) {
        if (k < off) {
            float ov = sv[k + off];
            int   oi = si[k + off];
            if (ov < sv[k] || (ov == sv[k] && oi < si[k])) { sv[k] = ov; si[k] = oi; }
        }
        __syncthreads();
    }
    if (k == 0) {
        g_code[b] = si[0];
        out_codes[b] = (float)si[0];
    }
}

// ============================================================================
// Pass 3: gather selected kv rows + loss partials (4-way hw split)
// ============================================================================
__global__ __launch_bounds__(256)
void gather_loss_kernel(const float* __restrict__ query,
                        float* __restrict__ out_sel) {
    const int blk = blockIdx.x;      // 0..95
    const int ch  = blockIdx.y;      // 0..3
    const int b   = blk / DQ;
    const int qq  = blk % DQ;
    const int tid = threadIdx.x;
    const int code = g_code[b];
    const int base = ch * 1024;

    const float* src = &g_kv[((size_t)b * MM + code * DQ + qq) * HWN + base];
    const float* qp  = &query[(size_t)(b * DQ + qq) * HWN + base];
    float*       dst = &out_sel[(size_t)(b * DQ + qq) * HWN + base];

    float s = 0.f;
    #pragma unroll
    for (int j = 0; j < 4; j++) {
        int i = tid + j * 256;
        float v = src[i];
        dst[i] = v;
        float d = v - qp[i];
        s += d * d;
    }
    __shared__ float red[256];
    red[tid] = s;
    __syncthreads();
    for (int off = 128; off > 0; off >>= 1) {
        if (tid < off) red[tid] += red[tid + off];
        __syncthreads();
    }
    if (tid == 0) g_loss[blk * 4 + ch] = red[0];
}

__global__ void loss_final_kernel(float* __restrict__ out_loss) {
    const int tid = threadIdx.x;     // 128
    float s = g_loss[tid] + g_loss[tid + 128] + g_loss[tid + 256];
    __shared__ float red[128];
    red[tid] = s;
    __syncthreads();
    for (int off = 64; off > 0; off >>= 1) {
        if (tid < off) red[tid] += red[tid + off];
        __syncthreads();
    }
    if (tid == 0) *out_loss = red[0] / (float)((size_t)BB * DQ * HWN);
}

// ============================================================================
extern "C" void kernel_launch(void* const* d_in, const int* in_sizes, int n_in,
                              void* d_out, int out_size) {
    const float* feat  = (const float*)d_in[0];
    const float* query = (const float*)d_in[1];
    const float* Wm    = (const float*)d_in[2];
    float* out = (float*)d_out;

    cudaFuncSetAttribute((const void*)kv_mma_kernel,
                         cudaFuncAttributeMaxDynamicSharedMemorySize, SMEM_TOT);

    wsplit_kernel<<<192, 256>>>(Wm);
    dim3 g1(NT, BB);
    kv_mma_kernel<<<g1, 256, SMEM_TOT>>>(feat, query);
    argmin_kernel<<<BB, KC>>>(out + (size_t)BB * DQ * HWN);
    dim3 g3(BB * DQ, 4);
    gather_loss_kernel<<<g3, 256>>>(query, out);
    loss_final_kernel<<<1, 128>>>(out + (size_t)BB * DQ * HWN + BB);
}

// round 8
// speedup vs baseline: 5.6126x; 1.0979x over previous
#include <cuda_runtime.h>
#include <cuda_fp16.h>
#include <cstdint>

#define BB   32
#define DIM  512
#define HWN  4096
#define KC   64
#define DQ   3
#define MM   192
#define NTILE 128           // hw per CTA
#define NT   32             // 4096/128
#define KSTAGE 32
#define NSTAGE 16           // 512/32

// dynamic smem layout
#define W_BUF_B   15360     // per buffer: hi only (192*80)
#define OFF_W     0
#define OFF_BH    30720     // fp16 feat [k32][n128] swizzled, 2 x 8192
#define SMEM_TOT  47104

// ---------------- scratch ----------------
__device__ __half   g_kv[(size_t)BB * MM * HWN];     // [b][m][hw]  (fp16)
__device__ float    g_part[BB * NT * KC];
__device__ float    g_loss[BB * DQ * 4];
__device__ unsigned g_Whi[MM * DIM / 2];             // f16x2, [m][kpair]

// ---------------- helpers ----------------
__device__ __forceinline__ uint32_t smem_u32(const void* p) {
    uint32_t a;
    asm("{ .reg .u64 t; cvta.to.shared.u64 t, %1; cvt.u32.u64 %0, t; }" : "=r"(a) : "l"(p));
    return a;
}
__device__ __forceinline__ void cp16(uint32_t smem, const void* gmem) {
    unsigned long long ga = (unsigned long long)__cvta_generic_to_global(gmem);
    asm volatile("cp.async.cg.shared.global [%0], [%1], 16;" :: "r"(smem), "l"(ga));
}
__device__ __forceinline__ void cp_commit() { asm volatile("cp.async.commit_group;"); }
__device__ __forceinline__ void cp_wait0() { asm volatile("cp.async.wait_group 0;" ::: "memory"); }

__device__ __forceinline__ void ldm4(unsigned* r, uint32_t a) {
    asm volatile("ldmatrix.sync.aligned.m8n8.x4.shared.b16 {%0,%1,%2,%3}, [%4];"
                 : "=r"(r[0]), "=r"(r[1]), "=r"(r[2]), "=r"(r[3]) : "r"(a));
}
__device__ __forceinline__ void ldm4t(unsigned* r, uint32_t a) {
    asm volatile("ldmatrix.sync.aligned.m8n8.x4.trans.shared.b16 {%0,%1,%2,%3}, [%4];"
                 : "=r"(r[0]), "=r"(r[1]), "=r"(r[2]), "=r"(r[3]) : "r"(a));
}
__device__ __forceinline__ void mma16816(float* c, const unsigned* a, const unsigned* b) {
    asm volatile("mma.sync.aligned.m16n8k16.row.col.f32.f16.f16.f32 "
                 "{%0,%1,%2,%3}, {%4,%5,%6,%7}, {%8,%9}, {%0,%1,%2,%3};"
                 : "+f"(c[0]), "+f"(c[1]), "+f"(c[2]), "+f"(c[3])
                 : "r"(a[0]), "r"(a[1]), "r"(a[2]), "r"(a[3]), "r"(b[0]), "r"(b[1]));
}
// pack fp16x2: {lo half = x0, hi half = x1}
__device__ __forceinline__ unsigned cvt2(float x0, float x1) {
    unsigned r;
    asm("cvt.rn.f16x2.f32 %0, %1, %2;" : "=r"(r) : "f"(x1), "f"(x0));
    return r;
}

// ============================================================================
// Pass 0: W fp32 -> fp16 packed k-pairs
// ============================================================================
__global__ void wsplit_kernel(const float* __restrict__ W) {
    int i = blockIdx.x * 256 + threadIdx.x;
    if (i >= MM * DIM / 2) return;
    g_Whi[i] = cvt2(W[2 * i], W[2 * i + 1]);
}

// ============================================================================
// Pass 1: C[m,hw] = W @ feat per batch via single-pass fp16 mma.sync.
// 256 threads, 8 warps = 4m x 2n (warp tile m48 x n64). Feat: direct
// LDG -> cvt -> STS, double-buffered fp16 B + W, ONE sync per stage.
// ============================================================================
__global__ __launch_bounds__(256)
void kv_mma_kernel(const float* __restrict__ feat,
                   const float* __restrict__ query) {
    extern __shared__ __align__(16) unsigned char dyn[];
    __shared__ float sdist[MM][2];

    const int tid  = threadIdx.x;
    const int b    = blockIdx.y;
    const int hw0  = blockIdx.x * NTILE;
    const int lane = tid & 31, wid = tid >> 5;
    const int warp_m = wid >> 1;          // 0..3 -> m offset *48
    const int warp_n = wid & 1;           // 0..1 -> hw offset *64
    const int g  = lane >> 2, tg = lane & 3;

    const uint32_t sbase = smem_u32(dyn);

    // feat conversion addressing: thread covers k=ck, n=[cn, cn+16)
    const int ck = tid >> 3;
    const int cn = (tid & 7) * 16;
    const uint32_t sts0 = (uint32_t)(ck * 256 + (((cn * 2)     ) ^ ((ck & 7) << 4)));
    const uint32_t sts1 = (uint32_t)(ck * 256 + (((cn * 2) + 16) ^ ((ck & 7) << 4)));

    auto issueW = [&](int s, int buf) {
        const uint32_t wb = sbase + OFF_W + (uint32_t)buf * W_BUF_B;
        #pragma unroll
        for (int j = 0; j < 3; j++) {                // W hi: 192 rows x 4 chunks
            int i = tid + j * 256;
            int m = i >> 2, c = i & 3;
            cp16(wb + m * 80 + c * 16, g_Whi + m * 256 + s * 16 + c * 4);
        }
    };

    float acc[3][8][4];
    #pragma unroll
    for (int mi = 0; mi < 3; mi++)
        #pragma unroll
        for (int ni = 0; ni < 8; ni++)
            #pragma unroll
            for (int r = 0; r < 4; r++) acc[mi][ni][r] = 0.f;

    // B ldmatrix lane addressing
    const int b_r      = lane & 7;
    const int b_khalf  = (lane >> 3) & 1;
    const int b_nhalf  = (lane >> 4) & 1;
    const uint32_t b_sw = (uint32_t)(b_r << 4);
    const uint32_t b_n0 = (uint32_t)(warp_n * 64 + b_nhalf * 8);

    // prefetch feat stage 0
    float4 f0, f1, f2, f3;
    {
        const float* fp = feat + ((size_t)(b * DIM + ck)) * HWN + hw0 + cn;
        f0 = *(const float4*)(fp);
        f1 = *(const float4*)(fp + 4);
        f2 = *(const float4*)(fp + 8);
        f3 = *(const float4*)(fp + 12);
    }
    issueW(0, 0); cp_commit();

    for (int s = 0; s < NSTAGE; s++) {
        const int buf = s & 1;
        const uint32_t bhb = sbase + OFF_BH + (uint32_t)buf * 8192;

        // ---- convert this stage's feat regs -> fp16 smem ----
        // (writes BH[buf], last read at stage s-2; single barrier below is
        //  sufficient ordering with double buffering)
        {
            unsigned h0 = cvt2(f0.x, f0.y), h1 = cvt2(f0.z, f0.w);
            unsigned h2 = cvt2(f1.x, f1.y), h3 = cvt2(f1.z, f1.w);
            unsigned h4 = cvt2(f2.x, f2.y), h5 = cvt2(f2.z, f2.w);
            unsigned h6 = cvt2(f3.x, f3.y), h7 = cvt2(f3.z, f3.w);
            *(uint4*)(dyn + OFF_BH + buf * 8192 + sts0) = make_uint4(h0, h1, h2, h3);
            *(uint4*)(dyn + OFF_BH + buf * 8192 + sts1) = make_uint4(h4, h5, h6, h7);
        }
        // ---- prefetch feat for next stage ----
        if (s + 1 < NSTAGE) {
            const float* fp = feat + ((size_t)(b * DIM + (s + 1) * KSTAGE + ck)) * HWN + hw0 + cn;
            f0 = *(const float4*)(fp);
            f1 = *(const float4*)(fp + 4);
            f2 = *(const float4*)(fp + 8);
            f3 = *(const float4*)(fp + 12);
        }
        cp_wait0();          // W for stage s landed
        __syncthreads();     // the ONLY barrier per stage
        if (s + 1 < NSTAGE) { issueW(s + 1, buf ^ 1); cp_commit(); }

        const uint32_t wbh = sbase + OFF_W + (uint32_t)buf * W_BUF_B;

        #pragma unroll
        for (int ks = 0; ks < 2; ks++) {
            // ---- B fragments via ldmatrix.trans: 4 quarters of n64 ----
            unsigned bh[4][4];
            {
                uint32_t k = (uint32_t)(ks * 16 + b_khalf * 8 + b_r);
                uint32_t rowb = bhb + k * 256;
                #pragma unroll
                for (int q = 0; q < 4; q++) {
                    uint32_t coff = (((b_n0 + q * 16) * 2) ^ b_sw);
                    ldm4t(bh[q], rowb + coff);
                }
            }
            // ---- A frags per m-tile + single-pass mma ----
            #pragma unroll
            for (int mi = 0; mi < 3; mi++) {
                uint32_t aoff = (uint32_t)(warp_m * 48 + mi * 16 + (lane & 15)) * 80
                              + ks * 32 + (lane >> 4) * 16;
                unsigned ah[4];
                ldm4(ah, wbh + aoff);
                #pragma unroll
                for (int ni = 0; ni < 8; ni++)
                    mma16816(acc[mi][ni], ah, &bh[ni >> 1][(ni & 1) * 2]);
            }
        }
    }

    // ---- epilogue: write kv (fp16) + fixed-order distance partials ----
    float2 qv[8][3];
    #pragma unroll
    for (int ni = 0; ni < 8; ni++) {
        int hw = hw0 + warp_n * 64 + ni * 8 + 2 * tg;
        #pragma unroll
        for (int qq = 0; qq < 3; qq++)
            qv[ni][qq] = *(const float2*)&query[((size_t)b * DQ + qq) * HWN + hw];
    }

    #pragma unroll
    for (int mi = 0; mi < 3; mi++) {
        int m0 = warp_m * 48 + mi * 16 + g;
        int q0 = m0 % 3, q1 = (m0 + 8) % 3;
        float d0 = 0.f, d1 = 0.f;
        #pragma unroll
        for (int ni = 0; ni < 8; ni++) {
            int hw = hw0 + warp_n * 64 + ni * 8 + 2 * tg;
            float2 p0 = make_float2(acc[mi][ni][0], acc[mi][ni][1]);
            float2 p1 = make_float2(acc[mi][ni][2], acc[mi][ni][3]);
            *(unsigned*)&g_kv[((size_t)b * MM + m0    ) * HWN + hw] = cvt2(p0.x, p0.y);
            *(unsigned*)&g_kv[((size_t)b * MM + m0 + 8) * HWN + hw] = cvt2(p1.x, p1.y);
            float e0 = p0.x - qv[ni][q0].x, e1 = p0.y - qv[ni][q0].y;
            d0 += e0 * e0 + e1 * e1;
            float f0e = p1.x - qv[ni][q1].x, f1e = p1.y - qv[ni][q1].y;
            d1 += f0e * f0e + f1e * f1e;
        }
        d0 += __shfl_xor_sync(0xffffffffu, d0, 1);
        d0 += __shfl_xor_sync(0xffffffffu, d0, 2);
        d1 += __shfl_xor_sync(0xffffffffu, d1, 1);
        d1 += __shfl_xor_sync(0xffffffffu, d1, 2);
        if (tg == 0) {
            sdist[m0][warp_n]     = d0;
            sdist[m0 + 8][warp_n] = d1;
        }
    }
    __syncthreads();
    if (tid < KC) {
        float s = 0.f;
        #pragma unroll
        for (int qq = 0; qq < 3; qq++)
            s += sdist[tid * 3 + qq][0] + sdist[tid * 3 + qq][1];
        g_part[((size_t)b * NT + blockIdx.x) * KC + tid] = s;
    }
}

// ============================================================================
// Pass 2: gather + loss with inline per-batch argmin (every block recomputes
// its batch's argmin from g_part — deterministic, first-min tie-break)
// ============================================================================
__global__ __launch_bounds__(256)
void gather_loss_kernel(const float* __restrict__ query,
                        float* __restrict__ out_sel,
                        float* __restrict__ out_codes) {
    const int blk = blockIdx.x;      // 0..95 (b*3+qq)
    const int ch  = blockIdx.y;      // 0..3
    const int b   = blk / DQ;
    const int qq  = blk % DQ;
    const int tid = threadIdx.x;

    __shared__ float sv[KC];
    __shared__ int   si[KC];
    if (tid < KC) {
        float s = 0.f;
        #pragma unroll 8
        for (int tt = 0; tt < NT; tt++)
            s += g_part[(b * NT + tt) * KC + tid];
        sv[tid] = s; si[tid] = tid;
    }
    __syncthreads();
    for (int off = 32; off > 0; off >>= 1) {
        if (tid < off) {
            float ov = sv[tid + off];
            int   oi = si[tid + off];
            if (ov < sv[tid] || (ov == sv[tid] && oi < si[tid])) { sv[tid] = ov; si[tid] = oi; }
        }
        __syncthreads();
    }
    const int code = si[0];
    if (tid == 0 && qq == 0 && ch == 0) out_codes[b] = (float)code;

    const int base = ch * 1024;
    const __half* src = &g_kv[((size_t)b * MM + code * DQ + qq) * HWN + base];
    const float*  qp  = &query[(size_t)(b * DQ + qq) * HWN + base];
    float*        dst = &out_sel[(size_t)(b * DQ + qq) * HWN + base];

    float s = 0.f;
    #pragma unroll
    for (int j = 0; j < 2; j++) {
        int i = (tid + j * 256) * 2;
        __half2 hv = *(const __half2*)(src + i);
        float2 v = __half22float2(hv);
        float2 qx = *(const float2*)(qp + i);
        *(float2*)(dst + i) = v;
        float d0 = v.x - qx.x, d1 = v.y - qx.y;
        s += d0 * d0 + d1 * d1;
    }
    __shared__ float red[256];
    red[tid] = s;
    __syncthreads();
    for (int off = 128; off > 0; off >>= 1) {
        if (tid < off) red[tid] += red[tid + off];
        __syncthreads();
    }
    if (tid == 0) g_loss[blk * 4 + ch] = red[0];
}

__global__ void loss_final_kernel(float* __restrict__ out_loss) {
    const int tid = threadIdx.x;     // 128
    float s = g_loss[tid] + g_loss[tid + 128] + g_loss[tid + 256];
    __shared__ float red[128];
    red[tid] = s;
    __syncthreads();
    for (int off = 64; off > 0; off >>= 1) {
        if (tid < off) red[tid] += red[tid + off];
        __syncthreads();
    }
    if (tid == 0) *out_loss = red[0] / (float)((size_t)BB * DQ * HWN);
}

// ============================================================================
extern "C" void kernel_launch(void* const* d_in, const int* in_sizes, int n_in,
                              void* d_out, int out_size) {
    const float* feat  = (const float*)d_in[0];
    const float* query = (const float*)d_in[1];
    const float* Wm    = (const float*)d_in[2];
    float* out = (float*)d_out;

    cudaFuncSetAttribute((const void*)kv_mma_kernel,
                         cudaFuncAttributeMaxDynamicSharedMemorySize, SMEM_TOT);

    wsplit_kernel<<<192, 256>>>(Wm);
    dim3 g1(NT, BB);
    kv_mma_kernel<<<g1, 256, SMEM_TOT>>>(feat, query);
    dim3 g3(BB * DQ, 4);
    gather_loss_kernel<<<g3, 256>>>(query, out, out + (size_t)BB * DQ * HWN);
    loss_final_kernel<<<1, 128>>>(out + (size_t)BB * DQ * HWN + BB);
}